// round 7
// baseline (speedup 1.0000x reference)
#include <cuda_runtime.h>
#include <math.h>

#define NN 10000
#define NE 160000
#define NG 64
#define EMB 128
#define MD 32
#define HID 642
#define EIN 321
#define PLD 644
#define CAT 768
#define EPSF 1e-5f

// ---------------- scratch (static device memory; no allocations) ----------------
__device__ float g_cat[NN * CAT];
__device__ float g_hcat[NN * CAT];
__device__ float g_Pa[NN * PLD];
__device__ float g_Pb[NN * PLD];
__device__ float g_seg[NN * MD];
__device__ float g_cnt[NN];
__device__ float g_z[NN * 160];
__device__ float g_h1[NN * 256];
__device__ float g_h2[NN * 128];
__device__ float g_f1[NN * 256];
__device__ float g_f2[NN * 256];
__device__ float g_f3[NN * 256];
__device__ float g_pool[NG * 256];
__device__ float g_pcnt[NG];

__device__ __forceinline__ float silu_f(float x) {
    return x * __fdividef(1.f, 1.f + __expf(-x));
}

__device__ __forceinline__ float to_tf32(float x) {
    unsigned u;
    asm("cvt.rna.tf32.f32 %0, %1;" : "=r"(u) : "f"(x));
    return __uint_as_float(u);
}

__device__ __forceinline__ void mma_tf32(float* c, unsigned a0, unsigned a1, unsigned a2, unsigned a3,
                                         unsigned b0, unsigned b1) {
    asm volatile(
        "mma.sync.aligned.m16n8k8.row.col.f32.tf32.tf32.f32 "
        "{%0,%1,%2,%3},{%4,%5,%6,%7},{%8,%9},{%0,%1,%2,%3};"
        : "+f"(c[0]), "+f"(c[1]), "+f"(c[2]), "+f"(c[3])
        : "r"(a0), "r"(a1), "r"(a2), "r"(a3), "r"(b0), "r"(b1));
}

// ---------------- small kernels ----------------
__global__ void k_zero_start() {
    int i = blockIdx.x * 256 + threadIdx.x;
    if (i < NN) g_cnt[i] = 0.f;
    if (i < NG * 256) g_pool[i] = 0.f;
    if (i < NG) g_pcnt[i] = 0.f;
    if (i < NN * MD) g_seg[i] = 0.f;
}
__global__ void k_deg(const int* __restrict__ eidx) {
    int e = blockIdx.x * 256 + threadIdx.x;
    if (e < NE) atomicAdd(&g_cnt[eidx[NE + e]], 1.f);
}
__global__ void k_embed(const int* __restrict__ atomids, const float* __restrict__ emb_w) {
    int i = blockIdx.x * 256 + threadIdx.x;
    if (i < NN * EMB) {
        int n = i >> 7, c = i & 127;
        g_cat[n * CAT + c] = emb_w[atomids[n] * EMB + c];
    }
}
__global__ void k_silucat() {
    int i = blockIdx.x * 256 + threadIdx.x;
    if (i < NN * CAT) g_hcat[i] = silu_f(g_cat[i]);
}
__global__ void k_pool(const int* __restrict__ batch) {
    int i = blockIdx.x * 256 + threadIdx.x;
    if (i < NN * 256) {
        int n = i >> 8, c = i & 255;
        atomicAdd(&g_pool[batch[n] * 256 + c], g_f3[i]);
    }
    if (i < NN) atomicAdd(&g_pcnt[batch[i]], 1.f);
}

// ---------------- 3xTF32 tensor-core GEMM (v1, proven): 128x64 tile ----------------
__global__ __launch_bounds__(256) void k_gemm3t(
    const float* __restrict__ A, const float* __restrict__ B,
    const float* __restrict__ bias, float* __restrict__ C,
    int M, int N, int K, int lda, int ldb, int ldc, int act) {
    __shared__ float sAh[128 * 20], sAl[128 * 20];
    __shared__ float sBh[16 * 68], sBl[16 * 68];
    int tid = threadIdx.x;
    int wid = tid >> 5, lane = tid & 31;
    int g = lane >> 2, tig = lane & 3;
    int r0 = wid << 4;
    int bm = blockIdx.y << 7, bn = blockIdx.x << 6;

    float acc[8][4];
#pragma unroll
    for (int t = 0; t < 8; t++)
#pragma unroll
        for (int u = 0; u < 4; u++) acc[t][u] = 0.f;

    for (int k0 = 0; k0 < K; k0 += 16) {
        __syncthreads();
        {
            int r = tid >> 1, c0 = (tid & 1) << 3;
            int gr = bm + r;
            float4 v0 = make_float4(0.f, 0.f, 0.f, 0.f), v1 = v0;
            if (gr < M) {
                const float* ap = A + (size_t)gr * lda + k0 + c0;
                v0 = *(const float4*)ap;
                v1 = *(const float4*)(ap + 4);
            }
            float* ph = &sAh[r * 20 + c0];
            float* pl = &sAl[r * 20 + c0];
            float h;
            h = to_tf32(v0.x); ph[0] = h; pl[0] = to_tf32(v0.x - h);
            h = to_tf32(v0.y); ph[1] = h; pl[1] = to_tf32(v0.y - h);
            h = to_tf32(v0.z); ph[2] = h; pl[2] = to_tf32(v0.z - h);
            h = to_tf32(v0.w); ph[3] = h; pl[3] = to_tf32(v0.w - h);
            h = to_tf32(v1.x); ph[4] = h; pl[4] = to_tf32(v1.x - h);
            h = to_tf32(v1.y); ph[5] = h; pl[5] = to_tf32(v1.y - h);
            h = to_tf32(v1.z); ph[6] = h; pl[6] = to_tf32(v1.z - h);
            h = to_tf32(v1.w); ph[7] = h; pl[7] = to_tf32(v1.w - h);
        }
        for (int idx = tid; idx < 16 * 64; idx += 256) {
            int kr = idx >> 6, nc = idx & 63;
            int gc = bn + nc;
            float v = (gc < N) ? B[(size_t)(k0 + kr) * ldb + gc] : 0.f;
            float hcv = to_tf32(v);
            sBh[kr * 68 + nc] = hcv;
            sBl[kr * 68 + nc] = to_tf32(v - hcv);
        }
        __syncthreads();
#pragma unroll
        for (int ks = 0; ks < 2; ks++) {
            int kk = ks << 3;
            unsigned ah0 = __float_as_uint(sAh[(r0 + g) * 20 + kk + tig]);
            unsigned ah1 = __float_as_uint(sAh[(r0 + g + 8) * 20 + kk + tig]);
            unsigned ah2 = __float_as_uint(sAh[(r0 + g) * 20 + kk + tig + 4]);
            unsigned ah3 = __float_as_uint(sAh[(r0 + g + 8) * 20 + kk + tig + 4]);
            unsigned al0 = __float_as_uint(sAl[(r0 + g) * 20 + kk + tig]);
            unsigned al1 = __float_as_uint(sAl[(r0 + g + 8) * 20 + kk + tig]);
            unsigned al2 = __float_as_uint(sAl[(r0 + g) * 20 + kk + tig + 4]);
            unsigned al3 = __float_as_uint(sAl[(r0 + g + 8) * 20 + kk + tig + 4]);
#pragma unroll
            for (int t = 0; t < 8; t++) {
                unsigned bh0 = __float_as_uint(sBh[(kk + tig) * 68 + (t << 3) + g]);
                unsigned bh1 = __float_as_uint(sBh[(kk + tig + 4) * 68 + (t << 3) + g]);
                unsigned bl0 = __float_as_uint(sBl[(kk + tig) * 68 + (t << 3) + g]);
                unsigned bl1 = __float_as_uint(sBl[(kk + tig + 4) * 68 + (t << 3) + g]);
                mma_tf32(acc[t], ah0, ah1, ah2, ah3, bh0, bh1);
                mma_tf32(acc[t], ah0, ah1, ah2, ah3, bl0, bl1);
                mma_tf32(acc[t], al0, al1, al2, al3, bh0, bh1);
            }
        }
    }

    int row0 = bm + r0 + g, row1 = row0 + 8;
#pragma unroll
    for (int t = 0; t < 8; t++) {
        int col = bn + (t << 3) + (tig << 1);
        if (col >= N) continue;
        float b0v = bias ? bias[col] : 0.f;
        float b1v = bias ? bias[col + 1] : 0.f;
        float v00 = acc[t][0] + b0v, v01 = acc[t][1] + b1v;
        float v10 = acc[t][2] + b0v, v11 = acc[t][3] + b1v;
        if (act) { v00 = silu_f(v00); v01 = silu_f(v01); v10 = silu_f(v10); v11 = silu_f(v11); }
        if (row0 < M) *(float2*)&C[(size_t)row0 * ldc + col] = make_float2(v00, v01);
        if (row1 < M) *(float2*)&C[(size_t)row1 * ldc + col] = make_float2(v10, v11);
    }
}

// ---------------- fused edge kernel v4: tf32 mma + register-double-buffered staging ----------------
// Per chunk: STS prefetched weights, coalesced PQ loads->regs, GEMM1 (hides PQ+next-W LDG),
// PQ->s_H, epilogue silu, GEMM2. Weight LDG for chunk c+1 overlaps full chunk c compute.
__global__ __launch_bounds__(256) void k_edge4(
    const int* __restrict__ eidx, const float* __restrict__ coords,
    const float* __restrict__ W1, const float* __restrict__ b1,
    const float* __restrict__ W2, const float* __restrict__ b2,
    const float* __restrict__ eng, const float* __restrict__ enb) {
    extern __shared__ float sm[];
    float* s_fe = sm;                       // 128 x 76
    float* s_H = sm + 128 * 76;             // 128 x 68
    float* s_W1c = s_H + 128 * 68;          // 72 x 68
    float* s_W2c = s_W1c + 72 * 68;         // 64 x 36
    float* s_b1 = s_W2c + 64 * 36;          // 648
    float* s_d2 = s_b1 + 648;               // 128
    int* s_src = (int*)(s_d2 + 128);        // 128
    int* s_dst = s_src + 128;               // 128

    int tid = threadIdx.x;
    int e0 = blockIdx.x << 7;

    if (tid < 128) {
        int e = e0 + tid;
        int s = eidx[e], d = eidx[NE + e];
        s_src[tid] = s; s_dst[tid] = d;
        float dx = coords[3 * s + 0] - coords[3 * d + 0];
        float dy = coords[3 * s + 1] - coords[3 * d + 1];
        float dz = coords[3 * s + 2] - coords[3 * d + 2];
        float d2 = dx * dx + dy * dy + dz * dz;
        s_d2[tid] = d2;
        s_fe[tid * 76 + 64] = to_tf32(d2);
#pragma unroll
        for (int j = 65; j < 72; j++) s_fe[tid * 76 + j] = 0.f;
    }
    for (int i = tid; i < 648; i += 256) s_b1[i] = (i < HID) ? b1[i] : 0.f;
    __syncthreads();
    for (int idx = tid; idx < 128 * 32; idx += 256) {
        int e = idx >> 5, i = idx & 31;
        float xs = s_d2[e] * __int_as_float((127 - i) << 23);
        float sv, cv;
        __sincosf(xs, &sv, &cv);
        s_fe[e * 76 + i] = to_tf32(sv);
        s_fe[e * 76 + 32 + i] = to_tf32(cv);
    }

    int wid = tid >> 5, lane = tid & 31;
    int g = lane >> 2, tig = lane & 3;
    int r0 = wid << 4;
    int rlo = r0 + g, rhi = r0 + g + 8;

    float acc[4][4];
#pragma unroll
    for (int t = 0; t < 4; t++)
#pragma unroll
        for (int u = 0; u < 4; u++) acc[t][u] = 0.f;

    // prefetch chunk 0 weights into registers
    float w1r[18], w2r[8];
#pragma unroll
    for (int i = 0; i < 18; i++) {
        int idx = tid + (i << 8); int k = idx >> 6, n = idx & 63;
        w1r[i] = (k < 65 && n < HID) ? W1[(256 + k) * HID + n] : 0.f;
    }
#pragma unroll
    for (int i = 0; i < 8; i++) {
        int idx = tid + (i << 8); int j = idx >> 5, n = idx & 31;
        w2r[i] = W2[j * MD + n];
    }

    for (int c = 0; c < 11; c++) {
        int cb = c << 6;
        __syncthreads();  // sync0: prev GEMM2 done (weight smem free); fe/b1 ready for c=0

        // store this chunk's weights (tf32) from registers
#pragma unroll
        for (int i = 0; i < 18; i++) {
            int idx = tid + (i << 8); int k = idx >> 6, n = idx & 63;
            s_W1c[k * 68 + n] = to_tf32(w1r[i]);
        }
#pragma unroll
        for (int i = 0; i < 8; i++) {
            int idx = tid + (i << 8); int j = idx >> 5, n = idx & 31;
            s_W2c[j * 36 + n] = to_tf32(w2r[i]);
        }

        // coalesced PQ loads into registers (latency hides under GEMM1 below)
        float4 pq[8];
#pragma unroll
        for (int i = 0; i < 8; i++) {
            int it = tid + (i << 8); int e = it >> 4, q = it & 15;
            int col = cb + (q << 2);
            float4 r = make_float4(0.f, 0.f, 0.f, 0.f);
            if (col < HID) {
                float4 pa = *(const float4*)&g_Pa[(size_t)s_dst[e] * PLD + col];
                float4 pb = *(const float4*)&g_Pb[(size_t)s_src[e] * PLD + col];
                r.x = pa.x + pb.x + s_b1[col];
                r.y = (col + 1 < HID) ? pa.y + pb.y + s_b1[col + 1] : 0.f;
                r.z = (col + 2 < HID) ? pa.z + pb.z + s_b1[col + 2] : 0.f;
                r.w = (col + 3 < HID) ? pa.w + pb.w + s_b1[col + 3] : 0.f;
            }
            pq[i] = r;
        }
        __syncthreads();  // sync1: weights visible

        // prefetch next chunk's weights (consumed next iteration -> full chunk of latency hiding)
        if (c < 10) {
            int cb2 = cb + 64;
#pragma unroll
            for (int i = 0; i < 18; i++) {
                int idx = tid + (i << 8); int k = idx >> 6, n = idx & 63; int gj = cb2 + n;
                w1r[i] = (k < 65 && gj < HID) ? W1[(256 + k) * HID + gj] : 0.f;
            }
#pragma unroll
            for (int i = 0; i < 8; i++) {
                int idx = tid + (i << 8); int j = idx >> 5, n = idx & 31; int gj = cb2 + j;
                w2r[i] = (gj < HID) ? W2[gj * MD + n] : 0.f;
            }
        }

        // GEMM1: c1 = FE @ W1c
        float c1[8][4];
#pragma unroll
        for (int t = 0; t < 8; t++)
#pragma unroll
            for (int u = 0; u < 4; u++) c1[t][u] = 0.f;
#pragma unroll
        for (int ks = 0; ks < 9; ks++) {
            int k0 = ks << 3;
            unsigned a0 = __float_as_uint(s_fe[rlo * 76 + k0 + tig]);
            unsigned a1 = __float_as_uint(s_fe[rhi * 76 + k0 + tig]);
            unsigned a2 = __float_as_uint(s_fe[rlo * 76 + k0 + tig + 4]);
            unsigned a3 = __float_as_uint(s_fe[rhi * 76 + k0 + tig + 4]);
#pragma unroll
            for (int t = 0; t < 8; t++) {
                unsigned b0v = __float_as_uint(s_W1c[(k0 + tig) * 68 + (t << 3) + g]);
                unsigned b1v = __float_as_uint(s_W1c[(k0 + tig + 4) * 68 + (t << 3) + g]);
                mma_tf32(c1[t], a0, a1, a2, a3, b0v, b1v);
            }
        }

        // drain PQ registers into s_H (loads have had all of GEMM1 to land)
#pragma unroll
        for (int i = 0; i < 8; i++) {
            int it = tid + (i << 8); int e = it >> 4, q = it & 15;
            *(float4*)&s_H[e * 68 + (q << 2)] = pq[i];
        }
        __syncthreads();  // sync2: PQ visible to fragment owners

        // epilogue: H = tf32(silu(c1 + PQ)), in place by owner
#pragma unroll
        for (int t = 0; t < 8; t++) {
            int col = (t << 3) + (tig << 1);
            int i00 = rlo * 68 + col;
            int i10 = rhi * 68 + col;
            s_H[i00] = to_tf32(silu_f(c1[t][0] + s_H[i00]));
            s_H[i00 + 1] = to_tf32(silu_f(c1[t][1] + s_H[i00 + 1]));
            s_H[i10] = to_tf32(silu_f(c1[t][2] + s_H[i10]));
            s_H[i10 + 1] = to_tf32(silu_f(c1[t][3] + s_H[i10 + 1]));
        }
        __syncthreads();  // sync3: H visible

        // GEMM2: acc += H @ W2c
#pragma unroll
        for (int ks = 0; ks < 8; ks++) {
            int k0 = ks << 3;
            unsigned a0 = __float_as_uint(s_H[rlo * 68 + k0 + tig]);
            unsigned a1 = __float_as_uint(s_H[rhi * 68 + k0 + tig]);
            unsigned a2 = __float_as_uint(s_H[rlo * 68 + k0 + tig + 4]);
            unsigned a3 = __float_as_uint(s_H[rhi * 68 + k0 + tig + 4]);
#pragma unroll
            for (int t = 0; t < 4; t++) {
                unsigned b0v = __float_as_uint(s_W2c[(k0 + tig) * 36 + (t << 3) + g]);
                unsigned b1v = __float_as_uint(s_W2c[(k0 + tig + 4) * 36 + (t << 3) + g]);
                mma_tf32(acc[t], a0, a1, a2, a3, b0v, b1v);
            }
        }
    }

    // message epilogue: silu(+b2), LN32 across quad, atomic segment-sum
    int dlo = s_dst[rlo], dhi = s_dst[rhi];
    float vlo[8], vhi[8];
    float Slo = 0.f, Shi = 0.f;
#pragma unroll
    for (int t = 0; t < 4; t++) {
        int col = (t << 3) + (tig << 1);
        float v0 = silu_f(acc[t][0] + b2[col]);
        float v1 = silu_f(acc[t][1] + b2[col + 1]);
        float v2 = silu_f(acc[t][2] + b2[col]);
        float v3 = silu_f(acc[t][3] + b2[col + 1]);
        vlo[t * 2] = v0; vlo[t * 2 + 1] = v1;
        vhi[t * 2] = v2; vhi[t * 2 + 1] = v3;
        Slo += v0 + v1; Shi += v2 + v3;
    }
    Slo += __shfl_xor_sync(0xffffffffu, Slo, 1);
    Slo += __shfl_xor_sync(0xffffffffu, Slo, 2);
    Shi += __shfl_xor_sync(0xffffffffu, Shi, 1);
    Shi += __shfl_xor_sync(0xffffffffu, Shi, 2);
    float mlo = Slo * (1.f / 32.f), mhi = Shi * (1.f / 32.f);
    float Vlo = 0.f, Vhi = 0.f;
#pragma unroll
    for (int u = 0; u < 8; u++) {
        float d0 = vlo[u] - mlo; Vlo += d0 * d0;
        float d1 = vhi[u] - mhi; Vhi += d1 * d1;
    }
    Vlo += __shfl_xor_sync(0xffffffffu, Vlo, 1);
    Vlo += __shfl_xor_sync(0xffffffffu, Vlo, 2);
    Vhi += __shfl_xor_sync(0xffffffffu, Vhi, 1);
    Vhi += __shfl_xor_sync(0xffffffffu, Vhi, 2);
    float ilo = rsqrtf(Vlo * (1.f / 32.f) + EPSF);
    float ihi = rsqrtf(Vhi * (1.f / 32.f) + EPSF);
#pragma unroll
    for (int t = 0; t < 4; t++) {
#pragma unroll
        for (int d = 0; d < 2; d++) {
            int col = (t << 3) + (tig << 1) + d;
            atomicAdd(&g_seg[dlo * MD + col], (vlo[t * 2 + d] - mlo) * ilo * eng[col] + enb[col]);
            atomicAdd(&g_seg[dhi * MD + col], (vhi[t * 2 + d] - mhi) * ihi * eng[col] + enb[col]);
        }
    }
}

// ---------------- node pre: m_i = LN(seg/cnt), z = [LN(feats)|m_i]; zeroes g_seg ----------------
__global__ void k_node_pre(int off, const float* __restrict__ eng, const float* __restrict__ enb,
                           const float* __restrict__ n1g, const float* __restrict__ n1b) {
    int node = blockIdx.x * 8 + (threadIdx.x >> 5);
    int lane = threadIdx.x & 31;
    if (node >= NN) return;

    float x = g_seg[node * MD + lane] / fmaxf(g_cnt[node], 1.f);
    g_seg[node * MD + lane] = 0.f;
    float S = x;
#pragma unroll
    for (int o = 16; o; o >>= 1) S += __shfl_xor_sync(0xffffffffu, S, o);
    float mean = S * (1.f / 32.f);
    float d = x - mean;
    float V = d * d;
#pragma unroll
    for (int o = 16; o; o >>= 1) V += __shfl_xor_sync(0xffffffffu, V, o);
    V *= (1.f / 32.f);
    g_z[node * 160 + 128 + lane] = d * rsqrtf(V + EPSF) * eng[lane] + enb[lane];

    float4 v = *(const float4*)&g_cat[node * CAT + off + lane * 4];
    S = v.x + v.y + v.z + v.w;
#pragma unroll
    for (int o = 16; o; o >>= 1) S += __shfl_xor_sync(0xffffffffu, S, o);
    mean = S * (1.f / 128.f);
    float dx = v.x - mean, dy = v.y - mean, dz = v.z - mean, dw = v.w - mean;
    V = dx * dx + dy * dy + dz * dz + dw * dw;
#pragma unroll
    for (int o = 16; o; o >>= 1) V += __shfl_xor_sync(0xffffffffu, V, o);
    V *= (1.f / 128.f);
    float inv = rsqrtf(V + EPSF);
    float4 g4 = *(const float4*)&n1g[lane * 4];
    float4 b4 = *(const float4*)&n1b[lane * 4];
    float4 o4;
    o4.x = dx * inv * g4.x + b4.x;
    o4.y = dy * inv * g4.y + b4.y;
    o4.z = dz * inv * g4.z + b4.z;
    o4.w = dw * inv * g4.w + b4.w;
    *(float4*)&g_z[node * 160 + lane * 4] = o4;
}

// ---------------- node post ----------------
__global__ void k_node_post(int off, const float* __restrict__ n2g, const float* __restrict__ n2b) {
    int node = blockIdx.x * 8 + (threadIdx.x >> 5);
    int lane = threadIdx.x & 31;
    if (node >= NN) return;
    float4 v = *(const float4*)&g_h2[node * 128 + lane * 4];
    float S = v.x + v.y + v.z + v.w;
#pragma unroll
    for (int o = 16; o; o >>= 1) S += __shfl_xor_sync(0xffffffffu, S, o);
    float mean = S * (1.f / 128.f);
    float dx = v.x - mean, dy = v.y - mean, dz = v.z - mean, dw = v.w - mean;
    float V = dx * dx + dy * dy + dz * dz + dw * dw;
#pragma unroll
    for (int o = 16; o; o >>= 1) V += __shfl_xor_sync(0xffffffffu, V, o);
    V *= (1.f / 128.f);
    float inv = rsqrtf(V + EPSF);
    float4 g4 = *(const float4*)&n2g[lane * 4];
    float4 b4 = *(const float4*)&n2b[lane * 4];
    float4 old = *(const float4*)&g_cat[node * CAT + off + lane * 4];
    float4 o4;
    o4.x = old.x + dx * inv * g4.x + b4.x;
    o4.y = old.y + dy * inv * g4.y + b4.y;
    o4.z = old.z + dz * inv * g4.z + b4.z;
    o4.w = old.w + dw * inv * g4.w + b4.w;
    *(float4*)&g_cat[node * CAT + off + 128 + lane * 4] = o4;
}

// ---------------- graph head ----------------
__global__ void k_graph(const float* __restrict__ g1W, const float* __restrict__ g1b,
                        const float* __restrict__ g2W, const float* __restrict__ g2b,
                        const float* __restrict__ g3W, const float* __restrict__ g3b,
                        float* __restrict__ out) {
    __shared__ float h[256], t[256];
    int g = blockIdx.x, tid = threadIdx.x;
    float c = fmaxf(g_pcnt[g], 1.f);
    h[tid] = g_pool[g * 256 + tid] / c;
    __syncthreads();
    float a = g1b[tid];
    for (int k = 0; k < 256; k++) a += h[k] * g1W[k * 256 + tid];
    t[tid] = silu_f(a);
    __syncthreads();
    h[tid] = t[tid];
    __syncthreads();
    a = g2b[tid];
    for (int k = 0; k < 256; k++) a += h[k] * g2W[k * 256 + tid];
    t[tid] = silu_f(a);
    __syncthreads();
    h[tid] = t[tid];
    __syncthreads();
    t[tid] = h[tid] * g3W[tid];
    __syncthreads();
    for (int s = 128; s; s >>= 1) {
        if (tid < s) t[tid] += t[tid + s];
        __syncthreads();
    }
    if (tid == 0) out[g] = t[0] + g3b[0];
}

// ---------------- launch ----------------
extern "C" void kernel_launch(void* const* d_in, const int* in_sizes, int n_in,
                              void* d_out, int out_size) {
    const int* atomids = (const int*)d_in[0];
    const float* coords = (const float*)d_in[1];
    const int* eidx = (const int*)d_in[2];
    const int* batch = (const int*)d_in[3];
    const float* emb_w = (const float*)d_in[4];
    const float* eW1 = (const float*)d_in[5];
    const float* eb1 = (const float*)d_in[6];
    const float* eW2 = (const float*)d_in[7];
    const float* eb2 = (const float*)d_in[8];
    const float* en_g = (const float*)d_in[9];
    const float* en_b = (const float*)d_in[10];
    const float* nn1_g = (const float*)d_in[11];
    const float* nn1_b = (const float*)d_in[12];
    const float* nW1 = (const float*)d_in[13];
    const float* nb1 = (const float*)d_in[14];
    const float* nW2 = (const float*)d_in[15];
    const float* nb2 = (const float*)d_in[16];
    const float* nn2_g = (const float*)d_in[17];
    const float* nn2_b = (const float*)d_in[18];
    const float* f1W = (const float*)d_in[19];
    const float* f1b = (const float*)d_in[20];
    const float* f2W = (const float*)d_in[21];
    const float* f2b = (const float*)d_in[22];
    const float* f3W = (const float*)d_in[23];
    const float* f3b = (const float*)d_in[24];
    const float* g1W = (const float*)d_in[25];
    const float* g1b = (const float*)d_in[26];
    const float* g2W = (const float*)d_in[27];
    const float* g2b = (const float*)d_in[28];
    const float* g3W = (const float*)d_in[29];
    const float* g3b = (const float*)d_in[30];
    float* out = (float*)d_out;

    const int smem_edge = (128 * 76 + 128 * 68 + 72 * 68 + 64 * 36 + 648 + 128 + 256) * 4;  // 106656
    cudaFuncSetAttribute(k_edge4, cudaFuncAttributeMaxDynamicSharedMemorySize, smem_edge);

    float *pcat, *phcat, *pPa, *pPb, *pz, *ph1, *ph2, *pf1, *pf2, *pf3;
    cudaGetSymbolAddress((void**)&pcat, g_cat);
    cudaGetSymbolAddress((void**)&phcat, g_hcat);
    cudaGetSymbolAddress((void**)&pPa, g_Pa);
    cudaGetSymbolAddress((void**)&pPb, g_Pb);
    cudaGetSymbolAddress((void**)&pz, g_z);
    cudaGetSymbolAddress((void**)&ph1, g_h1);
    cudaGetSymbolAddress((void**)&ph2, g_h2);
    cudaGetSymbolAddress((void**)&pf1, g_f1);
    cudaGetSymbolAddress((void**)&pf2, g_f2);
    cudaGetSymbolAddress((void**)&pf3, g_f3);

    k_zero_start<<<(NN * MD + 255) / 256, 256>>>();
    k_deg<<<(NE + 255) / 256, 256>>>(eidx);
    k_embed<<<(NN * EMB + 255) / 256, 256>>>(atomids, emb_w);

    const int MB = (NN + 127) / 128;  // 79

    for (int k = 0; k < 5; k++) {
        int off = 128 * k;
        k_gemm3t<<<dim3(11, MB), 256>>>(pcat + off, eW1 + (size_t)k * EIN * HID, nullptr, pPa,
                                        NN, HID, EMB, CAT, HID, PLD, 0);
        k_gemm3t<<<dim3(11, MB), 256>>>(pcat + off, eW1 + (size_t)k * EIN * HID + (size_t)EMB * HID,
                                        nullptr, pPb, NN, HID, EMB, CAT, HID, PLD, 0);
        k_edge4<<<NE / 128, 256, smem_edge>>>(eidx, coords,
                                              eW1 + (size_t)k * EIN * HID, eb1 + k * HID,
                                              eW2 + (size_t)k * HID * MD, eb2 + k * MD,
                                              en_g + k * MD, en_b + k * MD);
        k_node_pre<<<NN / 8, 256>>>(off, en_g + k * MD, en_b + k * MD,
                                    nn1_g + k * EMB, nn1_b + k * EMB);
        k_gemm3t<<<dim3(4, MB), 256>>>(pz, nW1 + (size_t)k * 160 * 256, nb1 + k * 256, ph1,
                                       NN, 256, 160, 160, 256, 256, 1);
        k_gemm3t<<<dim3(2, MB), 256>>>(ph1, nW2 + (size_t)k * 256 * 128, nb2 + k * 128, ph2,
                                       NN, 128, 256, 256, 128, 128, 0);
        k_node_post<<<NN / 8, 256>>>(off, nn2_g + k * EMB, nn2_b + k * EMB);
    }

    k_silucat<<<(NN * CAT + 255) / 256, 256>>>();
    k_gemm3t<<<dim3(4, MB), 256>>>(phcat, f1W, f1b, pf1, NN, 256, CAT, CAT, 256, 256, 1);
    k_gemm3t<<<dim3(4, MB), 256>>>(pf1, f2W, f2b, pf2, NN, 256, 256, 256, 256, 256, 1);
    k_gemm3t<<<dim3(4, MB), 256>>>(pf2, f3W, f3b, pf3, NN, 256, 256, 256, 256, 256, 1);
    k_pool<<<(NN * 256 + 255) / 256, 256>>>(batch);
    k_graph<<<NG, 256>>>(g1W, g1b, g2W, g2b, g3W, g3b, out);
}

// round 8
// speedup vs baseline: 1.1502x; 1.1502x over previous
#include <cuda_runtime.h>
#include <math.h>

#define NN 10000
#define NE 160000
#define NG 64
#define EMB 128
#define MD 32
#define HID 642
#define EIN 321
#define PLD 644
#define CAT 768
#define EPSF 1e-5f

// ---------------- scratch (static device memory; no allocations) ----------------
__device__ float g_cat[NN * CAT];
__device__ float g_hcat[NN * CAT];
__device__ float g_Pa[NN * PLD];
__device__ float g_Pb[NN * PLD];
__device__ float g_seg[NN * MD];
__device__ float g_cnt[NN];
__device__ float g_z[NN * 160];
__device__ float g_h1[NN * 256];
__device__ float g_h2[NN * 128];
__device__ float g_f1[NN * 256];
__device__ float g_f2[NN * 256];
__device__ float g_f3[NN * 256];
__device__ float g_pool[NG * 256];
__device__ float g_pcnt[NG];

__device__ __forceinline__ float silu_f(float x) {
    return x * __fdividef(1.f, 1.f + __expf(-x));
}

__device__ __forceinline__ float to_tf32(float x) {
    unsigned u;
    asm("cvt.rna.tf32.f32 %0, %1;" : "=r"(u) : "f"(x));
    return __uint_as_float(u);
}

__device__ __forceinline__ void mma_tf32(float* c, unsigned a0, unsigned a1, unsigned a2, unsigned a3,
                                         unsigned b0, unsigned b1) {
    asm volatile(
        "mma.sync.aligned.m16n8k8.row.col.f32.tf32.tf32.f32 "
        "{%0,%1,%2,%3},{%4,%5,%6,%7},{%8,%9},{%0,%1,%2,%3};"
        : "+f"(c[0]), "+f"(c[1]), "+f"(c[2]), "+f"(c[3])
        : "r"(a0), "r"(a1), "r"(a2), "r"(a3), "r"(b0), "r"(b1));
}

// ---------------- small kernels ----------------
__global__ void k_zero_start() {
    int i = blockIdx.x * 256 + threadIdx.x;
    if (i < NN) g_cnt[i] = 0.f;
    if (i < NG * 256) g_pool[i] = 0.f;
    if (i < NG) g_pcnt[i] = 0.f;
    if (i < NN * MD) g_seg[i] = 0.f;
}
__global__ void k_deg(const int* __restrict__ eidx) {
    int e = blockIdx.x * 256 + threadIdx.x;
    if (e < NE) atomicAdd(&g_cnt[eidx[NE + e]], 1.f);
}
__global__ void k_embed(const int* __restrict__ atomids, const float* __restrict__ emb_w) {
    int i = blockIdx.x * 256 + threadIdx.x;
    if (i < NN * EMB) {
        int n = i >> 7, c = i & 127;
        g_cat[n * CAT + c] = emb_w[atomids[n] * EMB + c];
    }
}
__global__ void k_silucat() {
    int i = blockIdx.x * 256 + threadIdx.x;
    if (i < NN * CAT) g_hcat[i] = silu_f(g_cat[i]);
}
__global__ void k_pool(const int* __restrict__ batch) {
    int i = blockIdx.x * 256 + threadIdx.x;
    if (i < NN * 256) {
        int n = i >> 8, c = i & 255;
        atomicAdd(&g_pool[batch[n] * 256 + c], g_f3[i]);
    }
    if (i < NN) atomicAdd(&g_pcnt[batch[i]], 1.f);
}

// ---------------- 3xTF32 tensor-core GEMM: 128x64 tile, fragment-major B ----------------
// B smem layout: [kr][g][t] (stride 72) so each thread's 8 t-values are 2x LDS.128.
__global__ __launch_bounds__(256) void k_gemm3t(
    const float* __restrict__ A, const float* __restrict__ B,
    const float* __restrict__ bias, float* __restrict__ C,
    int M, int N, int K, int lda, int ldb, int ldc, int act) {
    __shared__ __align__(16) float sAh[128 * 20], sAl[128 * 20];
    __shared__ __align__(16) float sBh[16 * 72], sBl[16 * 72];
    int tid = threadIdx.x;
    int wid = tid >> 5, lane = tid & 31;
    int g = lane >> 2, tig = lane & 3;
    int r0 = wid << 4;
    int bm = blockIdx.y << 7, bn = blockIdx.x << 6;

    float acc[8][4];
#pragma unroll
    for (int t = 0; t < 8; t++)
#pragma unroll
        for (int u = 0; u < 4; u++) acc[t][u] = 0.f;

    for (int k0 = 0; k0 < K; k0 += 16) {
        __syncthreads();
        {
            int r = tid >> 1, c0 = (tid & 1) << 3;
            int gr = bm + r;
            float4 v0 = make_float4(0.f, 0.f, 0.f, 0.f), v1 = v0;
            if (gr < M) {
                const float* ap = A + (size_t)gr * lda + k0 + c0;
                v0 = *(const float4*)ap;
                v1 = *(const float4*)(ap + 4);
            }
            float* ph = &sAh[r * 20 + c0];
            float* pl = &sAl[r * 20 + c0];
            float h;
            h = to_tf32(v0.x); ph[0] = h; pl[0] = to_tf32(v0.x - h);
            h = to_tf32(v0.y); ph[1] = h; pl[1] = to_tf32(v0.y - h);
            h = to_tf32(v0.z); ph[2] = h; pl[2] = to_tf32(v0.z - h);
            h = to_tf32(v0.w); ph[3] = h; pl[3] = to_tf32(v0.w - h);
            h = to_tf32(v1.x); ph[4] = h; pl[4] = to_tf32(v1.x - h);
            h = to_tf32(v1.y); ph[5] = h; pl[5] = to_tf32(v1.y - h);
            h = to_tf32(v1.z); ph[6] = h; pl[6] = to_tf32(v1.z - h);
            h = to_tf32(v1.w); ph[7] = h; pl[7] = to_tf32(v1.w - h);
        }
        // stage B tile 16x64, fragment-major: [kr][g][t]
        for (int idx = tid; idx < 16 * 64; idx += 256) {
            int kr = idx >> 6, nc = idx & 63;
            int gc = bn + nc;
            float v = (gc < N) ? B[(size_t)(k0 + kr) * ldb + gc] : 0.f;
            float hcv = to_tf32(v);
            int fi = kr * 72 + ((nc & 7) << 3) + (nc >> 3);
            sBh[fi] = hcv;
            sBl[fi] = to_tf32(v - hcv);
        }
        __syncthreads();
#pragma unroll
        for (int ks = 0; ks < 2; ks++) {
            int kk = ks << 3;
            unsigned ah0 = __float_as_uint(sAh[(r0 + g) * 20 + kk + tig]);
            unsigned ah1 = __float_as_uint(sAh[(r0 + g + 8) * 20 + kk + tig]);
            unsigned ah2 = __float_as_uint(sAh[(r0 + g) * 20 + kk + tig + 4]);
            unsigned ah3 = __float_as_uint(sAh[(r0 + g + 8) * 20 + kk + tig + 4]);
            unsigned al0 = __float_as_uint(sAl[(r0 + g) * 20 + kk + tig]);
            unsigned al1 = __float_as_uint(sAl[(r0 + g + 8) * 20 + kk + tig]);
            unsigned al2 = __float_as_uint(sAl[(r0 + g) * 20 + kk + tig + 4]);
            unsigned al3 = __float_as_uint(sAl[(r0 + g + 8) * 20 + kk + tig + 4]);
            int bi0 = (kk + tig) * 72 + (g << 3);
            int bi1 = (kk + tig + 4) * 72 + (g << 3);
#pragma unroll
            for (int half = 0; half < 2; half++) {
                float bh0[4], bh1[4], bl0[4], bl1[4];
                *(float4*)bh0 = *(const float4*)&sBh[bi0 + (half << 2)];
                *(float4*)bh1 = *(const float4*)&sBh[bi1 + (half << 2)];
                *(float4*)bl0 = *(const float4*)&sBl[bi0 + (half << 2)];
                *(float4*)bl1 = *(const float4*)&sBl[bi1 + (half << 2)];
#pragma unroll
                for (int tt = 0; tt < 4; tt++) {
                    int t = (half << 2) + tt;
                    mma_tf32(acc[t], ah0, ah1, ah2, ah3,
                             __float_as_uint(bh0[tt]), __float_as_uint(bh1[tt]));
                    mma_tf32(acc[t], ah0, ah1, ah2, ah3,
                             __float_as_uint(bl0[tt]), __float_as_uint(bl1[tt]));
                    mma_tf32(acc[t], al0, al1, al2, al3,
                             __float_as_uint(bh0[tt]), __float_as_uint(bh1[tt]));
                }
            }
        }
    }

    int row0 = bm + r0 + g, row1 = row0 + 8;
#pragma unroll
    for (int t = 0; t < 8; t++) {
        int col = bn + (t << 3) + (tig << 1);
        if (col >= N) continue;
        float b0v = bias ? bias[col] : 0.f;
        float b1v = bias ? bias[col + 1] : 0.f;
        float v00 = acc[t][0] + b0v, v01 = acc[t][1] + b1v;
        float v10 = acc[t][2] + b0v, v11 = acc[t][3] + b1v;
        if (act) { v00 = silu_f(v00); v01 = silu_f(v01); v10 = silu_f(v10); v11 = silu_f(v11); }
        if (row0 < M) *(float2*)&C[(size_t)row0 * ldc + col] = make_float2(v00, v01);
        if (row1 < M) *(float2*)&C[(size_t)row1 * ldc + col] = make_float2(v10, v11);
    }
}

// ---------------- fused edge kernel (round-4 proven structure, fragment-major weights) ----------------
__global__ __launch_bounds__(256) void k_edge2(
    const int* __restrict__ eidx, const float* __restrict__ coords,
    const float* __restrict__ W1, const float* __restrict__ b1,
    const float* __restrict__ W2, const float* __restrict__ b2,
    const float* __restrict__ eng, const float* __restrict__ enb) {
    extern __shared__ __align__(16) float sm[];
    float* s_fe = sm;                       // 128 x 76
    float* s_H = sm + 128 * 76;             // 128 x 68
    float* s_W1c = s_H + 128 * 68;          // 72 x 72 fragment-major [k][g][t]
    float* s_W2c = s_W1c + 72 * 72;         // 64 x 40 fragment-major [j][g][t] (t=0..3)
    float* s_b1 = s_W2c + 64 * 40;          // 648
    float* s_d2 = s_b1 + 648;               // 128
    int* s_src = (int*)(s_d2 + 128);        // 128
    int* s_dst = s_src + 128;               // 128

    int tid = threadIdx.x;
    int e0 = blockIdx.x << 7;

    if (tid < 128) {
        int e = e0 + tid;
        int s = eidx[e], d = eidx[NE + e];
        s_src[tid] = s; s_dst[tid] = d;
        float dx = coords[3 * s + 0] - coords[3 * d + 0];
        float dy = coords[3 * s + 1] - coords[3 * d + 1];
        float dz = coords[3 * s + 2] - coords[3 * d + 2];
        float d2 = dx * dx + dy * dy + dz * dz;
        s_d2[tid] = d2;
        s_fe[tid * 76 + 64] = to_tf32(d2);
#pragma unroll
        for (int j = 65; j < 72; j++) s_fe[tid * 76 + j] = 0.f;
    }
    for (int i = tid; i < 648; i += 256) s_b1[i] = (i < HID) ? b1[i] : 0.f;
    __syncthreads();
    for (int idx = tid; idx < 128 * 32; idx += 256) {
        int e = idx >> 5, i = idx & 31;
        float xs = s_d2[e] * __int_as_float((127 - i) << 23);
        float sv, cv;
        __sincosf(xs, &sv, &cv);
        s_fe[e * 76 + i] = to_tf32(sv);
        s_fe[e * 76 + 32 + i] = to_tf32(cv);
    }

    int wid = tid >> 5, lane = tid & 31;
    int g = lane >> 2, tig = lane & 3;
    int r0 = wid << 4;
    int rlo = r0 + g, rhi = r0 + g + 8;

    float acc[4][4];
#pragma unroll
    for (int t = 0; t < 4; t++)
#pragma unroll
        for (int u = 0; u < 4; u++) acc[t][u] = 0.f;

    for (int c = 0; c < 11; c++) {
        int cb = c << 6;
        __syncthreads();  // A: prev chunk done with weight smem / s_H
        // stage W1c (fourier rows of W1), tf32, fragment-major [k][g][t]
        for (int idx = tid; idx < 72 * 64; idx += 256) {
            int k = idx >> 6, n = idx & 63;
            int gj = cb + n;
            float v = (k < 65 && gj < HID) ? W1[(256 + k) * HID + gj] : 0.f;
            s_W1c[k * 72 + ((n & 7) << 3) + (n >> 3)] = to_tf32(v);
        }
        // stage W2c, tf32, fragment-major [j][g][t]
        for (int idx = tid; idx < 64 * 32; idx += 256) {
            int j = idx >> 5, n = idx & 31;
            int gj = cb + j;
            float v = (gj < HID) ? W2[gj * MD + n] : 0.f;
            s_W2c[j * 40 + ((n & 7) << 2) + (n >> 3)] = to_tf32(v);
        }
        // stage PQ = Pa[dst]+Pb[src]+b1 (exact fp32) into s_H
        for (int it = tid; it < 128 * 16; it += 256) {
            int e = it >> 4, q = it & 15;
            int col = cb + (q << 2);
            float4 r = make_float4(0.f, 0.f, 0.f, 0.f);
            if (col < HID) {
                float4 pa = *(const float4*)&g_Pa[(size_t)s_dst[e] * PLD + col];
                float4 pb = *(const float4*)&g_Pb[(size_t)s_src[e] * PLD + col];
                r.x = pa.x + pb.x + s_b1[col];
                r.y = (col + 1 < HID) ? pa.y + pb.y + s_b1[col + 1] : 0.f;
                r.z = (col + 2 < HID) ? pa.z + pb.z + s_b1[col + 2] : 0.f;
                r.w = (col + 3 < HID) ? pa.w + pb.w + s_b1[col + 3] : 0.f;
            }
            *(float4*)&s_H[e * 68 + (q << 2)] = r;
        }
        __syncthreads();  // B: staging visible

        // GEMM1: c1 = FE @ W1c
        float c1[8][4];
#pragma unroll
        for (int t = 0; t < 8; t++)
#pragma unroll
            for (int u = 0; u < 4; u++) c1[t][u] = 0.f;
#pragma unroll
        for (int ks = 0; ks < 9; ks++) {
            int k0 = ks << 3;
            unsigned a0 = __float_as_uint(s_fe[rlo * 76 + k0 + tig]);
            unsigned a1 = __float_as_uint(s_fe[rhi * 76 + k0 + tig]);
            unsigned a2 = __float_as_uint(s_fe[rlo * 76 + k0 + tig + 4]);
            unsigned a3 = __float_as_uint(s_fe[rhi * 76 + k0 + tig + 4]);
            int bi0 = (k0 + tig) * 72 + (g << 3);
            int bi1 = (k0 + tig + 4) * 72 + (g << 3);
#pragma unroll
            for (int half = 0; half < 2; half++) {
                float w0[4], w1[4];
                *(float4*)w0 = *(const float4*)&s_W1c[bi0 + (half << 2)];
                *(float4*)w1 = *(const float4*)&s_W1c[bi1 + (half << 2)];
#pragma unroll
                for (int tt = 0; tt < 4; tt++) {
                    mma_tf32(c1[(half << 2) + tt], a0, a1, a2, a3,
                             __float_as_uint(w0[tt]), __float_as_uint(w1[tt]));
                }
            }
        }
        // epilogue: H = tf32(silu(c1 + PQ)), in place by fragment owner
#pragma unroll
        for (int t = 0; t < 8; t++) {
            int col = (t << 3) + (tig << 1);
            int i00 = rlo * 68 + col;
            int i10 = rhi * 68 + col;
            s_H[i00] = to_tf32(silu_f(c1[t][0] + s_H[i00]));
            s_H[i00 + 1] = to_tf32(silu_f(c1[t][1] + s_H[i00 + 1]));
            s_H[i10] = to_tf32(silu_f(c1[t][2] + s_H[i10]));
            s_H[i10 + 1] = to_tf32(silu_f(c1[t][3] + s_H[i10 + 1]));
        }
        __syncthreads();  // C: H visible

        // GEMM2: acc += H @ W2c
#pragma unroll
        for (int ks = 0; ks < 8; ks++) {
            int k0 = ks << 3;
            unsigned a0 = __float_as_uint(s_H[rlo * 68 + k0 + tig]);
            unsigned a1 = __float_as_uint(s_H[rhi * 68 + k0 + tig]);
            unsigned a2 = __float_as_uint(s_H[rlo * 68 + k0 + tig + 4]);
            unsigned a3 = __float_as_uint(s_H[rhi * 68 + k0 + tig + 4]);
            float w0[4], w1[4];
            *(float4*)w0 = *(const float4*)&s_W2c[(k0 + tig) * 40 + (g << 2)];
            *(float4*)w1 = *(const float4*)&s_W2c[(k0 + tig + 4) * 40 + (g << 2)];
#pragma unroll
            for (int t = 0; t < 4; t++) {
                mma_tf32(acc[t], a0, a1, a2, a3,
                         __float_as_uint(w0[t]), __float_as_uint(w1[t]));
            }
        }
    }

    // message epilogue: silu(+b2), LN32 across quad, atomic segment-sum
    int dlo = s_dst[rlo], dhi = s_dst[rhi];
    float vlo[8], vhi[8];
    float Slo = 0.f, Shi = 0.f;
#pragma unroll
    for (int t = 0; t < 4; t++) {
        int col = (t << 3) + (tig << 1);
        float v0 = silu_f(acc[t][0] + b2[col]);
        float v1 = silu_f(acc[t][1] + b2[col + 1]);
        float v2 = silu_f(acc[t][2] + b2[col]);
        float v3 = silu_f(acc[t][3] + b2[col + 1]);
        vlo[t * 2] = v0; vlo[t * 2 + 1] = v1;
        vhi[t * 2] = v2; vhi[t * 2 + 1] = v3;
        Slo += v0 + v1; Shi += v2 + v3;
    }
    Slo += __shfl_xor_sync(0xffffffffu, Slo, 1);
    Slo += __shfl_xor_sync(0xffffffffu, Slo, 2);
    Shi += __shfl_xor_sync(0xffffffffu, Shi, 1);
    Shi += __shfl_xor_sync(0xffffffffu, Shi, 2);
    float mlo = Slo * (1.f / 32.f), mhi = Shi * (1.f / 32.f);
    float Vlo = 0.f, Vhi = 0.f;
#pragma unroll
    for (int u = 0; u < 8; u++) {
        float d0 = vlo[u] - mlo; Vlo += d0 * d0;
        float d1 = vhi[u] - mhi; Vhi += d1 * d1;
    }
    Vlo += __shfl_xor_sync(0xffffffffu, Vlo, 1);
    Vlo += __shfl_xor_sync(0xffffffffu, Vlo, 2);
    Vhi += __shfl_xor_sync(0xffffffffu, Vhi, 1);
    Vhi += __shfl_xor_sync(0xffffffffu, Vhi, 2);
    float ilo = rsqrtf(Vlo * (1.f / 32.f) + EPSF);
    float ihi = rsqrtf(Vhi * (1.f / 32.f) + EPSF);
#pragma unroll
    for (int t = 0; t < 4; t++) {
#pragma unroll
        for (int d = 0; d < 2; d++) {
            int col = (t << 3) + (tig << 1) + d;
            atomicAdd(&g_seg[dlo * MD + col], (vlo[t * 2 + d] - mlo) * ilo * eng[col] + enb[col]);
            atomicAdd(&g_seg[dhi * MD + col], (vhi[t * 2 + d] - mhi) * ihi * eng[col] + enb[col]);
        }
    }
}

// ---------------- node pre: m_i = LN(seg/cnt), z = [LN(feats)|m_i]; zeroes g_seg ----------------
__global__ void k_node_pre(int off, const float* __restrict__ eng, const float* __restrict__ enb,
                           const float* __restrict__ n1g, const float* __restrict__ n1b) {
    int node = blockIdx.x * 8 + (threadIdx.x >> 5);
    int lane = threadIdx.x & 31;
    if (node >= NN) return;

    float x = g_seg[node * MD + lane] / fmaxf(g_cnt[node], 1.f);
    g_seg[node * MD + lane] = 0.f;
    float S = x;
#pragma unroll
    for (int o = 16; o; o >>= 1) S += __shfl_xor_sync(0xffffffffu, S, o);
    float mean = S * (1.f / 32.f);
    float d = x - mean;
    float V = d * d;
#pragma unroll
    for (int o = 16; o; o >>= 1) V += __shfl_xor_sync(0xffffffffu, V, o);
    V *= (1.f / 32.f);
    g_z[node * 160 + 128 + lane] = d * rsqrtf(V + EPSF) * eng[lane] + enb[lane];

    float4 v = *(const float4*)&g_cat[node * CAT + off + lane * 4];
    S = v.x + v.y + v.z + v.w;
#pragma unroll
    for (int o = 16; o; o >>= 1) S += __shfl_xor_sync(0xffffffffu, S, o);
    mean = S * (1.f / 128.f);
    float dx = v.x - mean, dy = v.y - mean, dz = v.z - mean, dw = v.w - mean;
    V = dx * dx + dy * dy + dz * dz + dw * dw;
#pragma unroll
    for (int o = 16; o; o >>= 1) V += __shfl_xor_sync(0xffffffffu, V, o);
    V *= (1.f / 128.f);
    float inv = rsqrtf(V + EPSF);
    float4 g4 = *(const float4*)&n1g[lane * 4];
    float4 b4 = *(const float4*)&n1b[lane * 4];
    float4 o4;
    o4.x = dx * inv * g4.x + b4.x;
    o4.y = dy * inv * g4.y + b4.y;
    o4.z = dz * inv * g4.z + b4.z;
    o4.w = dw * inv * g4.w + b4.w;
    *(float4*)&g_z[node * 160 + lane * 4] = o4;
}

// ---------------- node post ----------------
__global__ void k_node_post(int off, const float* __restrict__ n2g, const float* __restrict__ n2b) {
    int node = blockIdx.x * 8 + (threadIdx.x >> 5);
    int lane = threadIdx.x & 31;
    if (node >= NN) return;
    float4 v = *(const float4*)&g_h2[node * 128 + lane * 4];
    float S = v.x + v.y + v.z + v.w;
#pragma unroll
    for (int o = 16; o; o >>= 1) S += __shfl_xor_sync(0xffffffffu, S, o);
    float mean = S * (1.f / 128.f);
    float dx = v.x - mean, dy = v.y - mean, dz = v.z - mean, dw = v.w - mean;
    float V = dx * dx + dy * dy + dz * dz + dw * dw;
#pragma unroll
    for (int o = 16; o; o >>= 1) V += __shfl_xor_sync(0xffffffffu, V, o);
    V *= (1.f / 128.f);
    float inv = rsqrtf(V + EPSF);
    float4 g4 = *(const float4*)&n2g[lane * 4];
    float4 b4 = *(const float4*)&n2b[lane * 4];
    float4 old = *(const float4*)&g_cat[node * CAT + off + lane * 4];
    float4 o4;
    o4.x = old.x + dx * inv * g4.x + b4.x;
    o4.y = old.y + dy * inv * g4.y + b4.y;
    o4.z = old.z + dz * inv * g4.z + b4.z;
    o4.w = old.w + dw * inv * g4.w + b4.w;
    *(float4*)&g_cat[node * CAT + off + 128 + lane * 4] = o4;
}

// ---------------- graph head ----------------
__global__ void k_graph(const float* __restrict__ g1W, const float* __restrict__ g1b,
                        const float* __restrict__ g2W, const float* __restrict__ g2b,
                        const float* __restrict__ g3W, const float* __restrict__ g3b,
                        float* __restrict__ out) {
    __shared__ float h[256], t[256];
    int g = blockIdx.x, tid = threadIdx.x;
    float c = fmaxf(g_pcnt[g], 1.f);
    h[tid] = g_pool[g * 256 + tid] / c;
    __syncthreads();
    float a = g1b[tid];
    for (int k = 0; k < 256; k++) a += h[k] * g1W[k * 256 + tid];
    t[tid] = silu_f(a);
    __syncthreads();
    h[tid] = t[tid];
    __syncthreads();
    a = g2b[tid];
    for (int k = 0; k < 256; k++) a += h[k] * g2W[k * 256 + tid];
    t[tid] = silu_f(a);
    __syncthreads();
    h[tid] = t[tid];
    __syncthreads();
    t[tid] = h[tid] * g3W[tid];
    __syncthreads();
    for (int s = 128; s; s >>= 1) {
        if (tid < s) t[tid] += t[tid + s];
        __syncthreads();
    }
    if (tid == 0) out[g] = t[0] + g3b[0];
}

// ---------------- launch ----------------
extern "C" void kernel_launch(void* const* d_in, const int* in_sizes, int n_in,
                              void* d_out, int out_size) {
    const int* atomids = (const int*)d_in[0];
    const float* coords = (const float*)d_in[1];
    const int* eidx = (const int*)d_in[2];
    const int* batch = (const int*)d_in[3];
    const float* emb_w = (const float*)d_in[4];
    const float* eW1 = (const float*)d_in[5];
    const float* eb1 = (const float*)d_in[6];
    const float* eW2 = (const float*)d_in[7];
    const float* eb2 = (const float*)d_in[8];
    const float* en_g = (const float*)d_in[9];
    const float* en_b = (const float*)d_in[10];
    const float* nn1_g = (const float*)d_in[11];
    const float* nn1_b = (const float*)d_in[12];
    const float* nW1 = (const float*)d_in[13];
    const float* nb1 = (const float*)d_in[14];
    const float* nW2 = (const float*)d_in[15];
    const float* nb2 = (const float*)d_in[16];
    const float* nn2_g = (const float*)d_in[17];
    const float* nn2_b = (const float*)d_in[18];
    const float* f1W = (const float*)d_in[19];
    const float* f1b = (const float*)d_in[20];
    const float* f2W = (const float*)d_in[21];
    const float* f2b = (const float*)d_in[22];
    const float* f3W = (const float*)d_in[23];
    const float* f3b = (const float*)d_in[24];
    const float* g1W = (const float*)d_in[25];
    const float* g1b = (const float*)d_in[26];
    const float* g2W = (const float*)d_in[27];
    const float* g2b = (const float*)d_in[28];
    const float* g3W = (const float*)d_in[29];
    const float* g3b = (const float*)d_in[30];
    float* out = (float*)d_out;

    // edge smem: fe(128*76) + H(128*68) + W1c(72*72) + W2c(64*40) + b1(648) + d2(128) + src/dst(256)
    const int smem_edge = (128 * 76 + 128 * 68 + 72 * 72 + 64 * 40 + 648 + 128 + 256) * 4;  // 108832
    cudaFuncSetAttribute(k_edge2, cudaFuncAttributeMaxDynamicSharedMemorySize, smem_edge);

    float *pcat, *phcat, *pPa, *pPb, *pz, *ph1, *ph2, *pf1, *pf2, *pf3;
    cudaGetSymbolAddress((void**)&pcat, g_cat);
    cudaGetSymbolAddress((void**)&phcat, g_hcat);
    cudaGetSymbolAddress((void**)&pPa, g_Pa);
    cudaGetSymbolAddress((void**)&pPb, g_Pb);
    cudaGetSymbolAddress((void**)&pz, g_z);
    cudaGetSymbolAddress((void**)&ph1, g_h1);
    cudaGetSymbolAddress((void**)&ph2, g_h2);
    cudaGetSymbolAddress((void**)&pf1, g_f1);
    cudaGetSymbolAddress((void**)&pf2, g_f2);
    cudaGetSymbolAddress((void**)&pf3, g_f3);

    k_zero_start<<<(NN * MD + 255) / 256, 256>>>();
    k_deg<<<(NE + 255) / 256, 256>>>(eidx);
    k_embed<<<(NN * EMB + 255) / 256, 256>>>(atomids, emb_w);

    const int MB = (NN + 127) / 128;  // 79

    for (int k = 0; k < 5; k++) {
        int off = 128 * k;
        k_gemm3t<<<dim3(11, MB), 256>>>(pcat + off, eW1 + (size_t)k * EIN * HID, nullptr, pPa,
                                        NN, HID, EMB, CAT, HID, PLD, 0);
        k_gemm3t<<<dim3(11, MB), 256>>>(pcat + off, eW1 + (size_t)k * EIN * HID + (size_t)EMB * HID,
                                        nullptr, pPb, NN, HID, EMB, CAT, HID, PLD, 0);
        k_edge2<<<NE / 128, 256, smem_edge>>>(eidx, coords,
                                              eW1 + (size_t)k * EIN * HID, eb1 + k * HID,
                                              eW2 + (size_t)k * HID * MD, eb2 + k * MD,
                                              en_g + k * MD, en_b + k * MD);
        k_node_pre<<<NN / 8, 256>>>(off, en_g + k * MD, en_b + k * MD,
                                    nn1_g + k * EMB, nn1_b + k * EMB);
        k_gemm3t<<<dim3(4, MB), 256>>>(pz, nW1 + (size_t)k * 160 * 256, nb1 + k * 256, ph1,
                                       NN, 256, 160, 160, 256, 256, 1);
        k_gemm3t<<<dim3(2, MB), 256>>>(ph1, nW2 + (size_t)k * 256 * 128, nb2 + k * 128, ph2,
                                       NN, 128, 256, 256, 128, 128, 0);
        k_node_post<<<NN / 8, 256>>>(off, nn2_g + k * EMB, nn2_b + k * EMB);
    }

    k_silucat<<<(NN * CAT + 255) / 256, 256>>>();
    k_gemm3t<<<dim3(4, MB), 256>>>(phcat, f1W, f1b, pf1, NN, 256, CAT, CAT, 256, 256, 1);
    k_gemm3t<<<dim3(4, MB), 256>>>(pf1, f2W, f2b, pf2, NN, 256, 256, 256, 256, 256, 1);
    k_gemm3t<<<dim3(4, MB), 256>>>(pf2, f3W, f3b, pf3, NN, 256, 256, 256, 256, 256, 1);
    k_pool<<<(NN * 256 + 255) / 256, 256>>>(batch);
    k_graph<<<NG, 256>>>(g1W, g1b, g2W, g2b, g3W, g3b, out);
}

// round 9
// speedup vs baseline: 1.1724x; 1.0193x over previous
#include <cuda_runtime.h>
#include <math.h>

#define NN 10000
#define NE 160000
#define NG 64
#define EMB 128
#define MD 32
#define HID 642
#define EIN 321
#define PLD 644
#define CAT 768
#define EPSF 1e-5f

// ---------------- scratch (static device memory; no allocations) ----------------
__device__ float g_cat[NN * CAT];
__device__ float g_Pa[NN * PLD];
__device__ float g_Pb[NN * PLD];
__device__ float g_Ah[NN * EMB];      // pre-split feats (hi)
__device__ float g_Al[NN * EMB];      // pre-split feats (lo)
__device__ float g_Wh[256 * HID];     // pre-split W1 rows 0..255 (hi)
__device__ float g_Wl[256 * HID];     // pre-split W1 rows 0..255 (lo)
__device__ float g_seg[NN * MD];
__device__ float g_cnt[NN];
__device__ float g_z[NN * 160];
__device__ float g_h1[NN * 256];
__device__ float g_h2[NN * 128];
__device__ float g_f1[NN * 256];
__device__ float g_f2[NN * 256];
__device__ float g_f3[NN * 256];
__device__ float g_pool[NG * 256];
__device__ float g_pcnt[NG];

__device__ __forceinline__ float silu_f(float x) {
    return x * __fdividef(1.f, 1.f + __expf(-x));
}

__device__ __forceinline__ float to_tf32(float x) {
    unsigned u;
    asm("cvt.rna.tf32.f32 %0, %1;" : "=r"(u) : "f"(x));
    return __uint_as_float(u);
}

__device__ __forceinline__ void mma_tf32(float* c, unsigned a0, unsigned a1, unsigned a2, unsigned a3,
                                         unsigned b0, unsigned b1) {
    asm volatile(
        "mma.sync.aligned.m16n8k8.row.col.f32.tf32.tf32.f32 "
        "{%0,%1,%2,%3},{%4,%5,%6,%7},{%8,%9},{%0,%1,%2,%3};"
        : "+f"(c[0]), "+f"(c[1]), "+f"(c[2]), "+f"(c[3])
        : "r"(a0), "r"(a1), "r"(a2), "r"(a3), "r"(b0), "r"(b1));
}

// ---------------- small kernels ----------------
__global__ void k_zero_start() {
    int i = blockIdx.x * 256 + threadIdx.x;
    if (i < NN) g_cnt[i] = 0.f;
    if (i < NG * 256) g_pool[i] = 0.f;
    if (i < NG) g_pcnt[i] = 0.f;
    if (i < NN * MD) g_seg[i] = 0.f;
}
__global__ void k_deg(const int* __restrict__ eidx) {
    int e = blockIdx.x * 256 + threadIdx.x;
    if (e < NE) atomicAdd(&g_cnt[eidx[NE + e]], 1.f);
}
// embed: write feats to g_cat AND pre-split copy to g_Ah/g_Al
__global__ void k_embed(const int* __restrict__ atomids, const float* __restrict__ emb_w) {
    int i = blockIdx.x * 256 + threadIdx.x;
    if (i < NN * EMB) {
        int n = i >> 7, c = i & 127;
        float v = emb_w[atomids[n] * EMB + c];
        g_cat[n * CAT + c] = v;
        float h = to_tf32(v);
        g_Ah[i] = h;
        g_Al[i] = to_tf32(v - h);
    }
}
// split first 256 rows of this layer's W1 into hi/lo
__global__ void k_split_w(const float* __restrict__ W1) {
    int i = blockIdx.x * 256 + threadIdx.x;
    if (i < 256 * HID) {
        float v = W1[i];
        float h = to_tf32(v);
        g_Wh[i] = h;
        g_Wl[i] = to_tf32(v - h);
    }
}
__global__ void k_pool(const int* __restrict__ batch) {
    int i = blockIdx.x * 256 + threadIdx.x;
    if (i < NN * 256) {
        int n = i >> 8, c = i & 255;
        atomicAdd(&g_pool[batch[n] * 256 + c], g_f3[i]);
    }
    if (i < NN) atomicAdd(&g_pcnt[batch[i]], 1.f);
}

// ---------------- pre-split 3xTF32 GEMM for Pa & Pb (fused, no CVTs in loop) ----------------
// grid (22, 79). blockIdx.x<11 -> Pa (W rows 0..127); else Pb (W rows 128..255).
__global__ __launch_bounds__(256) void k_gemm3p(
    const float* __restrict__ Ah, const float* __restrict__ Al,
    const float* __restrict__ Wh, const float* __restrict__ Wl,
    float* __restrict__ Ca, float* __restrict__ Cb) {
    __shared__ __align__(16) float sAh[128 * 20], sAl[128 * 20];
    __shared__ __align__(16) float sBh[16 * 72], sBl[16 * 72];
    int tid = threadIdx.x;
    int wid = tid >> 5, lane = tid & 31;
    int g = lane >> 2, tig = lane & 3;
    int r0 = wid << 4;
    int bm = blockIdx.y << 7;
    int half = (blockIdx.x >= 11) ? 1 : 0;
    int bn = (blockIdx.x - (half ? 11 : 0)) << 6;
    const float* Bh = Wh + (half ? (size_t)128 * HID : 0);
    const float* Bl = Wl + (half ? (size_t)128 * HID : 0);
    float* C = half ? Cb : Ca;

    float acc[8][4];
#pragma unroll
    for (int t = 0; t < 8; t++)
#pragma unroll
        for (int u = 0; u < 4; u++) acc[t][u] = 0.f;

    // A staging constants (one row per 2 threads, 8 floats each)
    int ar = tid >> 1, ac0 = (tid & 1) << 3;
    bool aok = (bm + ar) < NN;
    const float* aph = Ah + (size_t)(bm + ar) * EMB + ac0;
    const float* apl = Al + (size_t)(bm + ar) * EMB + ac0;
    float* sph = &sAh[ar * 20 + ac0];
    float* spl = &sAl[ar * 20 + ac0];
    // B staging constants (4 slots per thread)
    int bkr = tid >> 6;
    int bnc = tid & 63;
    int bgc = bn + bnc;
    bool bok = bgc < HID;
    const float* bph = Bh + (size_t)bkr * HID + bgc;
    const float* bpl = Bl + (size_t)bkr * HID + bgc;
    int bfi = bkr * 72 + ((bnc & 7) << 3) + (bnc >> 3);
    // fragment bases
    int arow_lo = (r0 + g) * 20, arow_hi = (r0 + g + 8) * 20;
    int bcol = g << 3;

    for (int k0 = 0; k0 < 128; k0 += 16) {
        __syncthreads();
        float4 h0 = make_float4(0.f, 0.f, 0.f, 0.f), h1 = h0, l0 = h0, l1 = h0;
        if (aok) {
            h0 = *(const float4*)aph; h1 = *(const float4*)(aph + 4);
            l0 = *(const float4*)apl; l1 = *(const float4*)(apl + 4);
        }
        *(float4*)sph = h0; *(float4*)(sph + 4) = h1;
        *(float4*)spl = l0; *(float4*)(spl + 4) = l1;
        aph += 16; apl += 16;
        {
            const float* ph = bph; const float* pl = bpl; int fi = bfi;
#pragma unroll
            for (int s = 0; s < 4; s++) {
                sBh[fi] = bok ? ph[0] : 0.f;
                sBl[fi] = bok ? pl[0] : 0.f;
                ph += 4 * HID; pl += 4 * HID; fi += 288;
            }
            bph += (size_t)16 * HID; bpl += (size_t)16 * HID;
        }
        __syncthreads();
#pragma unroll
        for (int ks = 0; ks < 2; ks++) {
            int kk = ks << 3;
            unsigned ah0 = __float_as_uint(sAh[arow_lo + kk + tig]);
            unsigned ah1 = __float_as_uint(sAh[arow_hi + kk + tig]);
            unsigned ah2 = __float_as_uint(sAh[arow_lo + kk + tig + 4]);
            unsigned ah3 = __float_as_uint(sAh[arow_hi + kk + tig + 4]);
            unsigned al0 = __float_as_uint(sAl[arow_lo + kk + tig]);
            unsigned al1 = __float_as_uint(sAl[arow_hi + kk + tig]);
            unsigned al2 = __float_as_uint(sAl[arow_lo + kk + tig + 4]);
            unsigned al3 = __float_as_uint(sAl[arow_hi + kk + tig + 4]);
            int bi0 = (kk + tig) * 72 + bcol;
            int bi1 = (kk + tig + 4) * 72 + bcol;
#pragma unroll
            for (int hlf = 0; hlf < 2; hlf++) {
                float bh0[4], bh1[4], bl0[4], bl1[4];
                *(float4*)bh0 = *(const float4*)&sBh[bi0 + (hlf << 2)];
                *(float4*)bh1 = *(const float4*)&sBh[bi1 + (hlf << 2)];
                *(float4*)bl0 = *(const float4*)&sBl[bi0 + (hlf << 2)];
                *(float4*)bl1 = *(const float4*)&sBl[bi1 + (hlf << 2)];
#pragma unroll
                for (int tt = 0; tt < 4; tt++) {
                    int t = (hlf << 2) + tt;
                    mma_tf32(acc[t], ah0, ah1, ah2, ah3,
                             __float_as_uint(bh0[tt]), __float_as_uint(bh1[tt]));
                    mma_tf32(acc[t], ah0, ah1, ah2, ah3,
                             __float_as_uint(bl0[tt]), __float_as_uint(bl1[tt]));
                    mma_tf32(acc[t], al0, al1, al2, al3,
                             __float_as_uint(bh0[tt]), __float_as_uint(bh1[tt]));
                }
            }
        }
    }

    int row0 = bm + r0 + g, row1 = row0 + 8;
#pragma unroll
    for (int t = 0; t < 8; t++) {
        int col = bn + (t << 3) + (tig << 1);
        if (col >= HID) continue;
        if (row0 < NN) *(float2*)&C[(size_t)row0 * PLD + col] = make_float2(acc[t][0], acc[t][1]);
        if (row1 < NN) *(float2*)&C[(size_t)row1 * PLD + col] = make_float2(acc[t][2], acc[t][3]);
    }
}

// ---------------- generic 3xTF32 GEMM (hoisted indices, optional input-silu) ----------------
__global__ __launch_bounds__(256) void k_gemm3t(
    const float* __restrict__ A, const float* __restrict__ B,
    const float* __restrict__ bias, float* __restrict__ C,
    int M, int N, int K, int lda, int ldb, int ldc, int act, int inact) {
    __shared__ __align__(16) float sAh[128 * 20], sAl[128 * 20];
    __shared__ __align__(16) float sBh[16 * 72], sBl[16 * 72];
    int tid = threadIdx.x;
    int wid = tid >> 5, lane = tid & 31;
    int g = lane >> 2, tig = lane & 3;
    int r0 = wid << 4;
    int bm = blockIdx.y << 7, bn = blockIdx.x << 6;

    float acc[8][4];
#pragma unroll
    for (int t = 0; t < 8; t++)
#pragma unroll
        for (int u = 0; u < 4; u++) acc[t][u] = 0.f;

    int ar = tid >> 1, ac0 = (tid & 1) << 3;
    bool aok = (bm + ar) < M;
    const float* aptr = A + (size_t)(bm + ar) * lda + ac0;
    float* sph = &sAh[ar * 20 + ac0];
    float* spl = &sAl[ar * 20 + ac0];
    int bkr = tid >> 6;
    int bnc = tid & 63;
    int bgc = bn + bnc;
    bool bok = bgc < N;
    const float* bptr = B + (size_t)bkr * ldb + bgc;
    int bfi = bkr * 72 + ((bnc & 7) << 3) + (bnc >> 3);
    int arow_lo = (r0 + g) * 20, arow_hi = (r0 + g + 8) * 20;
    int bcol = g << 3;

    for (int k0 = 0; k0 < K; k0 += 16) {
        __syncthreads();
        {
            float va[8];
#pragma unroll
            for (int j = 0; j < 8; j++) va[j] = 0.f;
            if (aok) {
                float4 t0 = *(const float4*)aptr;
                float4 t1 = *(const float4*)(aptr + 4);
                va[0] = t0.x; va[1] = t0.y; va[2] = t0.z; va[3] = t0.w;
                va[4] = t1.x; va[5] = t1.y; va[6] = t1.z; va[7] = t1.w;
            }
            if (inact) {
#pragma unroll
                for (int j = 0; j < 8; j++) va[j] = silu_f(va[j]);
            }
#pragma unroll
            for (int j = 0; j < 8; j++) {
                float h = to_tf32(va[j]);
                sph[j] = h;
                spl[j] = to_tf32(va[j] - h);
            }
            aptr += 16;
        }
        {
            const float* bp = bptr; int fi = bfi;
#pragma unroll
            for (int s = 0; s < 4; s++) {
                float v = bok ? bp[0] : 0.f;
                float h = to_tf32(v);
                sBh[fi] = h;
                sBl[fi] = to_tf32(v - h);
                bp += (size_t)4 * ldb; fi += 288;
            }
            bptr += (size_t)16 * ldb;
        }
        __syncthreads();
#pragma unroll
        for (int ks = 0; ks < 2; ks++) {
            int kk = ks << 3;
            unsigned ah0 = __float_as_uint(sAh[arow_lo + kk + tig]);
            unsigned ah1 = __float_as_uint(sAh[arow_hi + kk + tig]);
            unsigned ah2 = __float_as_uint(sAh[arow_lo + kk + tig + 4]);
            unsigned ah3 = __float_as_uint(sAh[arow_hi + kk + tig + 4]);
            unsigned al0 = __float_as_uint(sAl[arow_lo + kk + tig]);
            unsigned al1 = __float_as_uint(sAl[arow_hi + kk + tig]);
            unsigned al2 = __float_as_uint(sAl[arow_lo + kk + tig + 4]);
            unsigned al3 = __float_as_uint(sAl[arow_hi + kk + tig + 4]);
            int bi0 = (kk + tig) * 72 + bcol;
            int bi1 = (kk + tig + 4) * 72 + bcol;
#pragma unroll
            for (int hlf = 0; hlf < 2; hlf++) {
                float bh0[4], bh1[4], bl0[4], bl1[4];
                *(float4*)bh0 = *(const float4*)&sBh[bi0 + (hlf << 2)];
                *(float4*)bh1 = *(const float4*)&sBh[bi1 + (hlf << 2)];
                *(float4*)bl0 = *(const float4*)&sBl[bi0 + (hlf << 2)];
                *(float4*)bl1 = *(const float4*)&sBl[bi1 + (hlf << 2)];
#pragma unroll
                for (int tt = 0; tt < 4; tt++) {
                    int t = (hlf << 2) + tt;
                    mma_tf32(acc[t], ah0, ah1, ah2, ah3,
                             __float_as_uint(bh0[tt]), __float_as_uint(bh1[tt]));
                    mma_tf32(acc[t], ah0, ah1, ah2, ah3,
                             __float_as_uint(bl0[tt]), __float_as_uint(bl1[tt]));
                    mma_tf32(acc[t], al0, al1, al2, al3,
                             __float_as_uint(bh0[tt]), __float_as_uint(bh1[tt]));
                }
            }
        }
    }

    int row0 = bm + r0 + g, row1 = row0 + 8;
#pragma unroll
    for (int t = 0; t < 8; t++) {
        int col = bn + (t << 3) + (tig << 1);
        if (col >= N) continue;
        float b0v = bias ? bias[col] : 0.f;
        float b1v = bias ? bias[col + 1] : 0.f;
        float v00 = acc[t][0] + b0v, v01 = acc[t][1] + b1v;
        float v10 = acc[t][2] + b0v, v11 = acc[t][3] + b1v;
        if (act) { v00 = silu_f(v00); v01 = silu_f(v01); v10 = silu_f(v10); v11 = silu_f(v11); }
        if (row0 < M) *(float2*)&C[(size_t)row0 * ldc + col] = make_float2(v00, v01);
        if (row1 < M) *(float2*)&C[(size_t)row1 * ldc + col] = make_float2(v10, v11);
    }
}

// ---------------- fused edge kernel (round-8 proven, fragment-major weights) ----------------
__global__ __launch_bounds__(256) void k_edge2(
    const int* __restrict__ eidx, const float* __restrict__ coords,
    const float* __restrict__ W1, const float* __restrict__ b1,
    const float* __restrict__ W2, const float* __restrict__ b2,
    const float* __restrict__ eng, const float* __restrict__ enb) {
    extern __shared__ __align__(16) float sm[];
    float* s_fe = sm;                       // 128 x 76
    float* s_H = sm + 128 * 76;             // 128 x 68
    float* s_W1c = s_H + 128 * 68;          // 72 x 72 fragment-major [k][g][t]
    float* s_W2c = s_W1c + 72 * 72;         // 64 x 40 fragment-major [j][g][t]
    float* s_b1 = s_W2c + 64 * 40;          // 648
    float* s_d2 = s_b1 + 648;               // 128
    int* s_src = (int*)(s_d2 + 128);        // 128
    int* s_dst = s_src + 128;               // 128

    int tid = threadIdx.x;
    int e0 = blockIdx.x << 7;

    if (tid < 128) {
        int e = e0 + tid;
        int s = eidx[e], d = eidx[NE + e];
        s_src[tid] = s; s_dst[tid] = d;
        float dx = coords[3 * s + 0] - coords[3 * d + 0];
        float dy = coords[3 * s + 1] - coords[3 * d + 1];
        float dz = coords[3 * s + 2] - coords[3 * d + 2];
        float d2 = dx * dx + dy * dy + dz * dz;
        s_d2[tid] = d2;
        s_fe[tid * 76 + 64] = to_tf32(d2);
#pragma unroll
        for (int j = 65; j < 72; j++) s_fe[tid * 76 + j] = 0.f;
    }
    for (int i = tid; i < 648; i += 256) s_b1[i] = (i < HID) ? b1[i] : 0.f;
    __syncthreads();
    for (int idx = tid; idx < 128 * 32; idx += 256) {
        int e = idx >> 5, i = idx & 31;
        float xs = s_d2[e] * __int_as_float((127 - i) << 23);
        float sv, cv;
        __sincosf(xs, &sv, &cv);
        s_fe[e * 76 + i] = to_tf32(sv);
        s_fe[e * 76 + 32 + i] = to_tf32(cv);
    }

    int wid = tid >> 5, lane = tid & 31;
    int g = lane >> 2, tig = lane & 3;
    int r0 = wid << 4;
    int rlo = r0 + g, rhi = r0 + g + 8;

    float acc[4][4];
#pragma unroll
    for (int t = 0; t < 4; t++)
#pragma unroll
        for (int u = 0; u < 4; u++) acc[t][u] = 0.f;

    for (int c = 0; c < 11; c++) {
        int cb = c << 6;
        __syncthreads();  // A: prev chunk done with weight smem / s_H
        for (int idx = tid; idx < 72 * 64; idx += 256) {
            int k = idx >> 6, n = idx & 63;
            int gj = cb + n;
            float v = (k < 65 && gj < HID) ? W1[(256 + k) * HID + gj] : 0.f;
            s_W1c[k * 72 + ((n & 7) << 3) + (n >> 3)] = to_tf32(v);
        }
        for (int idx = tid; idx < 64 * 32; idx += 256) {
            int j = idx >> 5, n = idx & 31;
            int gj = cb + j;
            float v = (gj < HID) ? W2[gj * MD + n] : 0.f;
            s_W2c[j * 40 + ((n & 7) << 2) + (n >> 3)] = to_tf32(v);
        }
        for (int it = tid; it < 128 * 16; it += 256) {
            int e = it >> 4, q = it & 15;
            int col = cb + (q << 2);
            float4 r = make_float4(0.f, 0.f, 0.f, 0.f);
            if (col < HID) {
                float4 pa = *(const float4*)&g_Pa[(size_t)s_dst[e] * PLD + col];
                float4 pb = *(const float4*)&g_Pb[(size_t)s_src[e] * PLD + col];
                r.x = pa.x + pb.x + s_b1[col];
                r.y = (col + 1 < HID) ? pa.y + pb.y + s_b1[col + 1] : 0.f;
                r.z = (col + 2 < HID) ? pa.z + pb.z + s_b1[col + 2] : 0.f;
                r.w = (col + 3 < HID) ? pa.w + pb.w + s_b1[col + 3] : 0.f;
            }
            *(float4*)&s_H[e * 68 + (q << 2)] = r;
        }
        __syncthreads();  // B: staging visible

        float c1[8][4];
#pragma unroll
        for (int t = 0; t < 8; t++)
#pragma unroll
            for (int u = 0; u < 4; u++) c1[t][u] = 0.f;
#pragma unroll
        for (int ks = 0; ks < 9; ks++) {
            int k0 = ks << 3;
            unsigned a0 = __float_as_uint(s_fe[rlo * 76 + k0 + tig]);
            unsigned a1 = __float_as_uint(s_fe[rhi * 76 + k0 + tig]);
            unsigned a2 = __float_as_uint(s_fe[rlo * 76 + k0 + tig + 4]);
            unsigned a3 = __float_as_uint(s_fe[rhi * 76 + k0 + tig + 4]);
            int bi0 = (k0 + tig) * 72 + (g << 3);
            int bi1 = (k0 + tig + 4) * 72 + (g << 3);
#pragma unroll
            for (int half = 0; half < 2; half++) {
                float w0[4], w1[4];
                *(float4*)w0 = *(const float4*)&s_W1c[bi0 + (half << 2)];
                *(float4*)w1 = *(const float4*)&s_W1c[bi1 + (half << 2)];
#pragma unroll
                for (int tt = 0; tt < 4; tt++) {
                    mma_tf32(c1[(half << 2) + tt], a0, a1, a2, a3,
                             __float_as_uint(w0[tt]), __float_as_uint(w1[tt]));
                }
            }
        }
#pragma unroll
        for (int t = 0; t < 8; t++) {
            int col = (t << 3) + (tig << 1);
            int i00 = rlo * 68 + col;
            int i10 = rhi * 68 + col;
            s_H[i00] = to_tf32(silu_f(c1[t][0] + s_H[i00]));
            s_H[i00 + 1] = to_tf32(silu_f(c1[t][1] + s_H[i00 + 1]));
            s_H[i10] = to_tf32(silu_f(c1[t][2] + s_H[i10]));
            s_H[i10 + 1] = to_tf32(silu_f(c1[t][3] + s_H[i10 + 1]));
        }
        __syncthreads();  // C: H visible

#pragma unroll
        for (int ks = 0; ks < 8; ks++) {
            int k0 = ks << 3;
            unsigned a0 = __float_as_uint(s_H[rlo * 68 + k0 + tig]);
            unsigned a1 = __float_as_uint(s_H[rhi * 68 + k0 + tig]);
            unsigned a2 = __float_as_uint(s_H[rlo * 68 + k0 + tig + 4]);
            unsigned a3 = __float_as_uint(s_H[rhi * 68 + k0 + tig + 4]);
            float w0[4], w1[4];
            *(float4*)w0 = *(const float4*)&s_W2c[(k0 + tig) * 40 + (g << 2)];
            *(float4*)w1 = *(const float4*)&s_W2c[(k0 + tig + 4) * 40 + (g << 2)];
#pragma unroll
            for (int t = 0; t < 4; t++) {
                mma_tf32(acc[t], a0, a1, a2, a3,
                         __float_as_uint(w0[t]), __float_as_uint(w1[t]));
            }
        }
    }

    int dlo = s_dst[rlo], dhi = s_dst[rhi];
    float vlo[8], vhi[8];
    float Slo = 0.f, Shi = 0.f;
#pragma unroll
    for (int t = 0; t < 4; t++) {
        int col = (t << 3) + (tig << 1);
        float v0 = silu_f(acc[t][0] + b2[col]);
        float v1 = silu_f(acc[t][1] + b2[col + 1]);
        float v2 = silu_f(acc[t][2] + b2[col]);
        float v3 = silu_f(acc[t][3] + b2[col + 1]);
        vlo[t * 2] = v0; vlo[t * 2 + 1] = v1;
        vhi[t * 2] = v2; vhi[t * 2 + 1] = v3;
        Slo += v0 + v1; Shi += v2 + v3;
    }
    Slo += __shfl_xor_sync(0xffffffffu, Slo, 1);
    Slo += __shfl_xor_sync(0xffffffffu, Slo, 2);
    Shi += __shfl_xor_sync(0xffffffffu, Shi, 1);
    Shi += __shfl_xor_sync(0xffffffffu, Shi, 2);
    float mlo = Slo * (1.f / 32.f), mhi = Shi * (1.f / 32.f);
    float Vlo = 0.f, Vhi = 0.f;
#pragma unroll
    for (int u = 0; u < 8; u++) {
        float d0 = vlo[u] - mlo; Vlo += d0 * d0;
        float d1 = vhi[u] - mhi; Vhi += d1 * d1;
    }
    Vlo += __shfl_xor_sync(0xffffffffu, Vlo, 1);
    Vlo += __shfl_xor_sync(0xffffffffu, Vlo, 2);
    Vhi += __shfl_xor_sync(0xffffffffu, Vhi, 1);
    Vhi += __shfl_xor_sync(0xffffffffu, Vhi, 2);
    float ilo = rsqrtf(Vlo * (1.f / 32.f) + EPSF);
    float ihi = rsqrtf(Vhi * (1.f / 32.f) + EPSF);
#pragma unroll
    for (int t = 0; t < 4; t++) {
#pragma unroll
        for (int d = 0; d < 2; d++) {
            int col = (t << 3) + (tig << 1) + d;
            atomicAdd(&g_seg[dlo * MD + col], (vlo[t * 2 + d] - mlo) * ilo * eng[col] + enb[col]);
            atomicAdd(&g_seg[dhi * MD + col], (vhi[t * 2 + d] - mhi) * ihi * eng[col] + enb[col]);
        }
    }
}

// ---------------- node pre: m_i = LN(seg/cnt), z = [LN(feats)|m_i]; zeroes g_seg ----------------
__global__ void k_node_pre(int off, const float* __restrict__ eng, const float* __restrict__ enb,
                           const float* __restrict__ n1g, const float* __restrict__ n1b) {
    int node = blockIdx.x * 8 + (threadIdx.x >> 5);
    int lane = threadIdx.x & 31;
    if (node >= NN) return;

    float x = g_seg[node * MD + lane] / fmaxf(g_cnt[node], 1.f);
    g_seg[node * MD + lane] = 0.f;
    float S = x;
#pragma unroll
    for (int o = 16; o; o >>= 1) S += __shfl_xor_sync(0xffffffffu, S, o);
    float mean = S * (1.f / 32.f);
    float d = x - mean;
    float V = d * d;
#pragma unroll
    for (int o = 16; o; o >>= 1) V += __shfl_xor_sync(0xffffffffu, V, o);
    V *= (1.f / 32.f);
    g_z[node * 160 + 128 + lane] = d * rsqrtf(V + EPSF) * eng[lane] + enb[lane];

    float4 v = *(const float4*)&g_cat[node * CAT + off + lane * 4];
    S = v.x + v.y + v.z + v.w;
#pragma unroll
    for (int o = 16; o; o >>= 1) S += __shfl_xor_sync(0xffffffffu, S, o);
    mean = S * (1.f / 128.f);
    float dx = v.x - mean, dy = v.y - mean, dz = v.z - mean, dw = v.w - mean;
    V = dx * dx + dy * dy + dz * dz + dw * dw;
#pragma unroll
    for (int o = 16; o; o >>= 1) V += __shfl_xor_sync(0xffffffffu, V, o);
    V *= (1.f / 128.f);
    float inv = rsqrtf(V + EPSF);
    float4 g4 = *(const float4*)&n1g[lane * 4];
    float4 b4 = *(const float4*)&n1b[lane * 4];
    float4 o4;
    o4.x = dx * inv * g4.x + b4.x;
    o4.y = dy * inv * g4.y + b4.y;
    o4.z = dz * inv * g4.z + b4.z;
    o4.w = dw * inv * g4.w + b4.w;
    *(float4*)&g_z[node * 160 + lane * 4] = o4;
}

// ---------------- node post: g_cat update + pre-split feats for next layer's Pa/Pb ----------------
__global__ void k_node_post(int off, const float* __restrict__ n2g, const float* __restrict__ n2b) {
    int node = blockIdx.x * 8 + (threadIdx.x >> 5);
    int lane = threadIdx.x & 31;
    if (node >= NN) return;
    float4 v = *(const float4*)&g_h2[node * 128 + lane * 4];
    float S = v.x + v.y + v.z + v.w;
#pragma unroll
    for (int o = 16; o; o >>= 1) S += __shfl_xor_sync(0xffffffffu, S, o);
    float mean = S * (1.f / 128.f);
    float dx = v.x - mean, dy = v.y - mean, dz = v.z - mean, dw = v.w - mean;
    float V = dx * dx + dy * dy + dz * dz + dw * dw;
#pragma unroll
    for (int o = 16; o; o >>= 1) V += __shfl_xor_sync(0xffffffffu, V, o);
    V *= (1.f / 128.f);
    float inv = rsqrtf(V + EPSF);
    float4 g4 = *(const float4*)&n2g[lane * 4];
    float4 b4 = *(const float4*)&n2b[lane * 4];
    float4 old = *(const float4*)&g_cat[node * CAT + off + lane * 4];
    float4 o4;
    o4.x = old.x + dx * inv * g4.x + b4.x;
    o4.y = old.y + dy * inv * g4.y + b4.y;
    o4.z = old.z + dz * inv * g4.z + b4.z;
    o4.w = old.w + dw * inv * g4.w + b4.w;
    *(float4*)&g_cat[node * CAT + off + 128 + lane * 4] = o4;
    // pre-split for next layer's k_gemm3p
    int base = node * EMB + lane * 4;
    float h;
    h = to_tf32(o4.x); g_Ah[base + 0] = h; g_Al[base + 0] = to_tf32(o4.x - h);
    h = to_tf32(o4.y); g_Ah[base + 1] = h; g_Al[base + 1] = to_tf32(o4.y - h);
    h = to_tf32(o4.z); g_Ah[base + 2] = h; g_Al[base + 2] = to_tf32(o4.z - h);
    h = to_tf32(o4.w); g_Ah[base + 3] = h; g_Al[base + 3] = to_tf32(o4.w - h);
}

// ---------------- graph head ----------------
__global__ void k_graph(const float* __restrict__ g1W, const float* __restrict__ g1b,
                        const float* __restrict__ g2W, const float* __restrict__ g2b,
                        const float* __restrict__ g3W, const float* __restrict__ g3b,
                        float* __restrict__ out) {
    __shared__ float h[256], t[256];
    int g = blockIdx.x, tid = threadIdx.x;
    float c = fmaxf(g_pcnt[g], 1.f);
    h[tid] = g_pool[g * 256 + tid] / c;
    __syncthreads();
    float a = g1b[tid];
    for (int k = 0; k < 256; k++) a += h[k] * g1W[k * 256 + tid];
    t[tid] = silu_f(a);
    __syncthreads();
    h[tid] = t[tid];
    __syncthreads();
    a = g2b[tid];
    for (int k = 0; k < 256; k++) a += h[k] * g2W[k * 256 + tid];
    t[tid] = silu_f(a);
    __syncthreads();
    h[tid] = t[tid];
    __syncthreads();
    t[tid] = h[tid] * g3W[tid];
    __syncthreads();
    for (int s = 128; s; s >>= 1) {
        if (tid < s) t[tid] += t[tid + s];
        __syncthreads();
    }
    if (tid == 0) out[g] = t[0] + g3b[0];
}

// ---------------- launch ----------------
extern "C" void kernel_launch(void* const* d_in, const int* in_sizes, int n_in,
                              void* d_out, int out_size) {
    const int* atomids = (const int*)d_in[0];
    const float* coords = (const float*)d_in[1];
    const int* eidx = (const int*)d_in[2];
    const int* batch = (const int*)d_in[3];
    const float* emb_w = (const float*)d_in[4];
    const float* eW1 = (const float*)d_in[5];
    const float* eb1 = (const float*)d_in[6];
    const float* eW2 = (const float*)d_in[7];
    const float* eb2 = (const float*)d_in[8];
    const float* en_g = (const float*)d_in[9];
    const float* en_b = (const float*)d_in[10];
    const float* nn1_g = (const float*)d_in[11];
    const float* nn1_b = (const float*)d_in[12];
    const float* nW1 = (const float*)d_in[13];
    const float* nb1 = (const float*)d_in[14];
    const float* nW2 = (const float*)d_in[15];
    const float* nb2 = (const float*)d_in[16];
    const float* nn2_g = (const float*)d_in[17];
    const float* nn2_b = (const float*)d_in[18];
    const float* f1W = (const float*)d_in[19];
    const float* f1b = (const float*)d_in[20];
    const float* f2W = (const float*)d_in[21];
    const float* f2b = (const float*)d_in[22];
    const float* f3W = (const float*)d_in[23];
    const float* f3b = (const float*)d_in[24];
    const float* g1W = (const float*)d_in[25];
    const float* g1b = (const float*)d_in[26];
    const float* g2W = (const float*)d_in[27];
    const float* g2b = (const float*)d_in[28];
    const float* g3W = (const float*)d_in[29];
    const float* g3b = (const float*)d_in[30];
    float* out = (float*)d_out;

    const int smem_edge = (128 * 76 + 128 * 68 + 72 * 72 + 64 * 40 + 648 + 128 + 256) * 4;  // 108832
    cudaFuncSetAttribute(k_edge2, cudaFuncAttributeMaxDynamicSharedMemorySize, smem_edge);

    float *pcat, *pPa, *pPb, *pAh, *pAl, *pWh, *pWl, *pz, *ph1, *ph2, *pf1, *pf2, *pf3;
    cudaGetSymbolAddress((void**)&pcat, g_cat);
    cudaGetSymbolAddress((void**)&pPa, g_Pa);
    cudaGetSymbolAddress((void**)&pPb, g_Pb);
    cudaGetSymbolAddress((void**)&pAh, g_Ah);
    cudaGetSymbolAddress((void**)&pAl, g_Al);
    cudaGetSymbolAddress((void**)&pWh, g_Wh);
    cudaGetSymbolAddress((void**)&pWl, g_Wl);
    cudaGetSymbolAddress((void**)&pz, g_z);
    cudaGetSymbolAddress((void**)&ph1, g_h1);
    cudaGetSymbolAddress((void**)&ph2, g_h2);
    cudaGetSymbolAddress((void**)&pf1, g_f1);
    cudaGetSymbolAddress((void**)&pf2, g_f2);
    cudaGetSymbolAddress((void**)&pf3, g_f3);

    k_zero_start<<<(NN * MD + 255) / 256, 256>>>();
    k_deg<<<(NE + 255) / 256, 256>>>(eidx);
    k_embed<<<(NN * EMB + 255) / 256, 256>>>(atomids, emb_w);

    const int MB = (NN + 127) / 128;  // 79

    for (int k = 0; k < 5; k++) {
        int off = 128 * k;
        k_split_w<<<(256 * HID + 255) / 256, 256>>>(eW1 + (size_t)k * EIN * HID);
        k_gemm3p<<<dim3(22, MB), 256>>>(pAh, pAl, pWh, pWl, pPa, pPb);
        k_edge2<<<NE / 128, 256, smem_edge>>>(eidx, coords,
                                              eW1 + (size_t)k * EIN * HID, eb1 + k * HID,
                                              eW2 + (size_t)k * HID * MD, eb2 + k * MD,
                                              en_g + k * MD, en_b + k * MD);
        k_node_pre<<<NN / 8, 256>>>(off, en_g + k * MD, en_b + k * MD,
                                    nn1_g + k * EMB, nn1_b + k * EMB);
        k_gemm3t<<<dim3(4, MB), 256>>>(pz, nW1 + (size_t)k * 160 * 256, nb1 + k * 256, ph1,
                                       NN, 256, 160, 160, 256, 256, 1, 0);
        k_gemm3t<<<dim3(2, MB), 256>>>(ph1, nW2 + (size_t)k * 256 * 128, nb2 + k * 128, ph2,
                                       NN, 128, 256, 256, 128, 128, 0, 0);
        k_node_post<<<NN / 8, 256>>>(off, nn2_g + k * EMB, nn2_b + k * EMB);
    }

    k_gemm3t<<<dim3(4, MB), 256>>>(pcat, f1W, f1b, pf1, NN, 256, CAT, CAT, 256, 256, 1, 1);
    k_gemm3t<<<dim3(4, MB), 256>>>(pf1, f2W, f2b, pf2, NN, 256, 256, 256, 256, 256, 1, 0);
    k_gemm3t<<<dim3(4, MB), 256>>>(pf2, f3W, f3b, pf3, NN, 256, 256, 256, 256, 256, 1, 0);
    k_pool<<<(NN * 256 + 255) / 256, 256>>>(batch);
    k_graph<<<NG, 256>>>(g1W, g1b, g2W, g2b, g3W, g3b, out);
}

// round 10
// speedup vs baseline: 1.1917x; 1.0164x over previous
#include <cuda_runtime.h>
#include <math.h>

#define NN 10000
#define NE 160000
#define NG 64
#define EMB 128
#define MD 32
#define HID 642
#define EIN 321
#define PLD 644
#define CAT 768
#define EPSF 1e-5f

// ---------------- scratch (static device memory; no allocations) ----------------
__device__ float g_cat[NN * CAT];
__device__ float g_Pa[NN * PLD];
__device__ float g_Pb[NN * PLD];
__device__ float g_Ah[NN * EMB];
__device__ float g_Al[NN * EMB];
__device__ float g_Wh[256 * HID];
__device__ float g_Wl[256 * HID];
__device__ float g_seg[NN * MD];
__device__ float g_cnt[NN];
__device__ float g_z[NN * 160];
__device__ float g_h1[NN * 256];
__device__ float g_h2[NN * 128];
__device__ float g_f1[NN * 256];
__device__ float g_f2[NN * 256];
__device__ float g_f3[NN * 256];
__device__ float g_pool[NG * 256];
__device__ float g_pcnt[NG];

__device__ __forceinline__ float silu_f(float x) {
    return x * __fdividef(1.f, 1.f + __expf(-x));
}

__device__ __forceinline__ float to_tf32(float x) {
    unsigned u;
    asm("cvt.rna.tf32.f32 %0, %1;" : "=r"(u) : "f"(x));
    return __uint_as_float(u);
}

__device__ __forceinline__ void mma_tf32(float* c, unsigned a0, unsigned a1, unsigned a2, unsigned a3,
                                         unsigned b0, unsigned b1) {
    asm volatile(
        "mma.sync.aligned.m16n8k8.row.col.f32.tf32.tf32.f32 "
        "{%0,%1,%2,%3},{%4,%5,%6,%7},{%8,%9},{%0,%1,%2,%3};"
        : "+f"(c[0]), "+f"(c[1]), "+f"(c[2]), "+f"(c[3])
        : "r"(a0), "r"(a1), "r"(a2), "r"(a3), "r"(b0), "r"(b1));
}

// ---------------- small kernels ----------------
__global__ void k_zero_start() {
    int i = blockIdx.x * 256 + threadIdx.x;
    if (i < NN) g_cnt[i] = 0.f;
    if (i < NG * 256) g_pool[i] = 0.f;
    if (i < NG) g_pcnt[i] = 0.f;
    if (i < NN * MD) g_seg[i] = 0.f;
}
__global__ void k_deg(const int* __restrict__ eidx) {
    int e = blockIdx.x * 256 + threadIdx.x;
    if (e < NE) atomicAdd(&g_cnt[eidx[NE + e]], 1.f);
}
__global__ void k_embed(const int* __restrict__ atomids, const float* __restrict__ emb_w) {
    int i = blockIdx.x * 256 + threadIdx.x;
    if (i < NN * EMB) {
        int n = i >> 7, c = i & 127;
        float v = emb_w[atomids[n] * EMB + c];
        g_cat[n * CAT + c] = v;
        float h = to_tf32(v);
        g_Ah[i] = h;
        g_Al[i] = to_tf32(v - h);
    }
}
__global__ void k_split_w(const float* __restrict__ W1) {
    int i = blockIdx.x * 256 + threadIdx.x;
    if (i < 256 * HID) {
        float v = W1[i];
        float h = to_tf32(v);
        g_Wh[i] = h;
        g_Wl[i] = to_tf32(v - h);
    }
}
__global__ void k_pool(const int* __restrict__ batch) {
    int i = blockIdx.x * 256 + threadIdx.x;
    if (i < NN * 256) {
        int n = i >> 8, c = i & 255;
        atomicAdd(&g_pool[batch[n] * 256 + c], g_f3[i]);
    }
    if (i < NN) atomicAdd(&g_pcnt[batch[i]], 1.f);
}

// ---------------- pre-split 3xTF32 GEMM for Pa & Pb (fused) ----------------
__global__ __launch_bounds__(256) void k_gemm3p(
    const float* __restrict__ Ah, const float* __restrict__ Al,
    const float* __restrict__ Wh, const float* __restrict__ Wl,
    float* __restrict__ Ca, float* __restrict__ Cb) {
    __shared__ __align__(16) float sAh[128 * 20], sAl[128 * 20];
    __shared__ __align__(16) float sBh[16 * 72], sBl[16 * 72];
    int tid = threadIdx.x;
    int wid = tid >> 5, lane = tid & 31;
    int g = lane >> 2, tig = lane & 3;
    int r0 = wid << 4;
    int bm = blockIdx.y << 7;
    int half = (blockIdx.x >= 11) ? 1 : 0;
    int bn = (blockIdx.x - (half ? 11 : 0)) << 6;
    const float* Bh = Wh + (half ? (size_t)128 * HID : 0);
    const float* Bl = Wl + (half ? (size_t)128 * HID : 0);
    float* C = half ? Cb : Ca;

    float acc[8][4];
#pragma unroll
    for (int t = 0; t < 8; t++)
#pragma unroll
        for (int u = 0; u < 4; u++) acc[t][u] = 0.f;

    int ar = tid >> 1, ac0 = (tid & 1) << 3;
    bool aok = (bm + ar) < NN;
    const float* aph = Ah + (size_t)(bm + ar) * EMB + ac0;
    const float* apl = Al + (size_t)(bm + ar) * EMB + ac0;
    float* sph = &sAh[ar * 20 + ac0];
    float* spl = &sAl[ar * 20 + ac0];
    int bkr = tid >> 6;
    int bnc = tid & 63;
    int bgc = bn + bnc;
    bool bok = bgc < HID;
    const float* bph = Bh + (size_t)bkr * HID + bgc;
    const float* bpl = Bl + (size_t)bkr * HID + bgc;
    int bfi = bkr * 72 + ((bnc & 7) << 3) + (bnc >> 3);
    int arow_lo = (r0 + g) * 20, arow_hi = (r0 + g + 8) * 20;
    int bcol = g << 3;

    for (int k0 = 0; k0 < 128; k0 += 16) {
        __syncthreads();
        float4 h0 = make_float4(0.f, 0.f, 0.f, 0.f), h1 = h0, l0 = h0, l1 = h0;
        if (aok) {
            h0 = *(const float4*)aph; h1 = *(const float4*)(aph + 4);
            l0 = *(const float4*)apl; l1 = *(const float4*)(apl + 4);
        }
        *(float4*)sph = h0; *(float4*)(sph + 4) = h1;
        *(float4*)spl = l0; *(float4*)(spl + 4) = l1;
        aph += 16; apl += 16;
        {
            const float* ph = bph; const float* pl = bpl; int fi = bfi;
#pragma unroll
            for (int s = 0; s < 4; s++) {
                sBh[fi] = bok ? ph[0] : 0.f;
                sBl[fi] = bok ? pl[0] : 0.f;
                ph += 4 * HID; pl += 4 * HID; fi += 288;
            }
            bph += (size_t)16 * HID; bpl += (size_t)16 * HID;
        }
        __syncthreads();
#pragma unroll
        for (int ks = 0; ks < 2; ks++) {
            int kk = ks << 3;
            unsigned ah0 = __float_as_uint(sAh[arow_lo + kk + tig]);
            unsigned ah1 = __float_as_uint(sAh[arow_hi + kk + tig]);
            unsigned ah2 = __float_as_uint(sAh[arow_lo + kk + tig + 4]);
            unsigned ah3 = __float_as_uint(sAh[arow_hi + kk + tig + 4]);
            unsigned al0 = __float_as_uint(sAl[arow_lo + kk + tig]);
            unsigned al1 = __float_as_uint(sAl[arow_hi + kk + tig]);
            unsigned al2 = __float_as_uint(sAl[arow_lo + kk + tig + 4]);
            unsigned al3 = __float_as_uint(sAl[arow_hi + kk + tig + 4]);
            int bi0 = (kk + tig) * 72 + bcol;
            int bi1 = (kk + tig + 4) * 72 + bcol;
#pragma unroll
            for (int hlf = 0; hlf < 2; hlf++) {
                float bh0[4], bh1[4], bl0[4], bl1[4];
                *(float4*)bh0 = *(const float4*)&sBh[bi0 + (hlf << 2)];
                *(float4*)bh1 = *(const float4*)&sBh[bi1 + (hlf << 2)];
                *(float4*)bl0 = *(const float4*)&sBl[bi0 + (hlf << 2)];
                *(float4*)bl1 = *(const float4*)&sBl[bi1 + (hlf << 2)];
#pragma unroll
                for (int tt = 0; tt < 4; tt++) {
                    int t = (hlf << 2) + tt;
                    mma_tf32(acc[t], ah0, ah1, ah2, ah3,
                             __float_as_uint(bh0[tt]), __float_as_uint(bh1[tt]));
                    mma_tf32(acc[t], ah0, ah1, ah2, ah3,
                             __float_as_uint(bl0[tt]), __float_as_uint(bl1[tt]));
                    mma_tf32(acc[t], al0, al1, al2, al3,
                             __float_as_uint(bh0[tt]), __float_as_uint(bh1[tt]));
                }
            }
        }
    }

    int row0 = bm + r0 + g, row1 = row0 + 8;
#pragma unroll
    for (int t = 0; t < 8; t++) {
        int col = bn + (t << 3) + (tig << 1);
        if (col >= HID) continue;
        if (row0 < NN) *(float2*)&C[(size_t)row0 * PLD + col] = make_float2(acc[t][0], acc[t][1]);
        if (row1 < NN) *(float2*)&C[(size_t)row1 * PLD + col] = make_float2(acc[t][2], acc[t][3]);
    }
}

// ---------------- generic 3xTF32 GEMM ----------------
__global__ __launch_bounds__(256) void k_gemm3t(
    const float* __restrict__ A, const float* __restrict__ B,
    const float* __restrict__ bias, float* __restrict__ C,
    int M, int N, int K, int lda, int ldb, int ldc, int act, int inact) {
    __shared__ __align__(16) float sAh[128 * 20], sAl[128 * 20];
    __shared__ __align__(16) float sBh[16 * 72], sBl[16 * 72];
    int tid = threadIdx.x;
    int wid = tid >> 5, lane = tid & 31;
    int g = lane >> 2, tig = lane & 3;
    int r0 = wid << 4;
    int bm = blockIdx.y << 7, bn = blockIdx.x << 6;

    float acc[8][4];
#pragma unroll
    for (int t = 0; t < 8; t++)
#pragma unroll
        for (int u = 0; u < 4; u++) acc[t][u] = 0.f;

    int ar = tid >> 1, ac0 = (tid & 1) << 3;
    bool aok = (bm + ar) < M;
    const float* aptr = A + (size_t)(bm + ar) * lda + ac0;
    float* sph = &sAh[ar * 20 + ac0];
    float* spl = &sAl[ar * 20 + ac0];
    int bkr = tid >> 6;
    int bnc = tid & 63;
    int bgc = bn + bnc;
    bool bok = bgc < N;
    const float* bptr = B + (size_t)bkr * ldb + bgc;
    int bfi = bkr * 72 + ((bnc & 7) << 3) + (bnc >> 3);
    int arow_lo = (r0 + g) * 20, arow_hi = (r0 + g + 8) * 20;
    int bcol = g << 3;

    for (int k0 = 0; k0 < K; k0 += 16) {
        __syncthreads();
        {
            float va[8];
#pragma unroll
            for (int j = 0; j < 8; j++) va[j] = 0.f;
            if (aok) {
                float4 t0 = *(const float4*)aptr;
                float4 t1 = *(const float4*)(aptr + 4);
                va[0] = t0.x; va[1] = t0.y; va[2] = t0.z; va[3] = t0.w;
                va[4] = t1.x; va[5] = t1.y; va[6] = t1.z; va[7] = t1.w;
            }
            if (inact) {
#pragma unroll
                for (int j = 0; j < 8; j++) va[j] = silu_f(va[j]);
            }
#pragma unroll
            for (int j = 0; j < 8; j++) {
                float h = to_tf32(va[j]);
                sph[j] = h;
                spl[j] = to_tf32(va[j] - h);
            }
            aptr += 16;
        }
        {
            const float* bp = bptr; int fi = bfi;
#pragma unroll
            for (int s = 0; s < 4; s++) {
                float v = bok ? bp[0] : 0.f;
                float h = to_tf32(v);
                sBh[fi] = h;
                sBl[fi] = to_tf32(v - h);
                bp += (size_t)4 * ldb; fi += 288;
            }
            bptr += (size_t)16 * ldb;
        }
        __syncthreads();
#pragma unroll
        for (int ks = 0; ks < 2; ks++) {
            int kk = ks << 3;
            unsigned ah0 = __float_as_uint(sAh[arow_lo + kk + tig]);
            unsigned ah1 = __float_as_uint(sAh[arow_hi + kk + tig]);
            unsigned ah2 = __float_as_uint(sAh[arow_lo + kk + tig + 4]);
            unsigned ah3 = __float_as_uint(sAh[arow_hi + kk + tig + 4]);
            unsigned al0 = __float_as_uint(sAl[arow_lo + kk + tig]);
            unsigned al1 = __float_as_uint(sAl[arow_hi + kk + tig]);
            unsigned al2 = __float_as_uint(sAl[arow_lo + kk + tig + 4]);
            unsigned al3 = __float_as_uint(sAl[arow_hi + kk + tig + 4]);
            int bi0 = (kk + tig) * 72 + bcol;
            int bi1 = (kk + tig + 4) * 72 + bcol;
#pragma unroll
            for (int hlf = 0; hlf < 2; hlf++) {
                float bh0[4], bh1[4], bl0[4], bl1[4];
                *(float4*)bh0 = *(const float4*)&sBh[bi0 + (hlf << 2)];
                *(float4*)bh1 = *(const float4*)&sBh[bi1 + (hlf << 2)];
                *(float4*)bl0 = *(const float4*)&sBl[bi0 + (hlf << 2)];
                *(float4*)bl1 = *(const float4*)&sBl[bi1 + (hlf << 2)];
#pragma unroll
                for (int tt = 0; tt < 4; tt++) {
                    int t = (hlf << 2) + tt;
                    mma_tf32(acc[t], ah0, ah1, ah2, ah3,
                             __float_as_uint(bh0[tt]), __float_as_uint(bh1[tt]));
                    mma_tf32(acc[t], ah0, ah1, ah2, ah3,
                             __float_as_uint(bl0[tt]), __float_as_uint(bl1[tt]));
                    mma_tf32(acc[t], al0, al1, al2, al3,
                             __float_as_uint(bh0[tt]), __float_as_uint(bh1[tt]));
                }
            }
        }
    }

    int row0 = bm + r0 + g, row1 = row0 + 8;
#pragma unroll
    for (int t = 0; t < 8; t++) {
        int col = bn + (t << 3) + (tig << 1);
        if (col >= N) continue;
        float b0v = bias ? bias[col] : 0.f;
        float b1v = bias ? bias[col + 1] : 0.f;
        float v00 = acc[t][0] + b0v, v01 = acc[t][1] + b1v;
        float v10 = acc[t][2] + b0v, v11 = acc[t][3] + b1v;
        if (act) { v00 = silu_f(v00); v01 = silu_f(v01); v10 = silu_f(v10); v11 = silu_f(v11); }
        if (row0 < M) *(float2*)&C[(size_t)row0 * ldc + col] = make_float2(v00, v01);
        if (row1 < M) *(float2*)&C[(size_t)row1 * ldc + col] = make_float2(v10, v11);
    }
}

// ---------------- fused edge kernel v5: fe fragments in registers, s_H aliased over s_fe,
// smem 74KB -> 2 CTAs/SM ----------------
__global__ __launch_bounds__(256, 2) void k_edge2(
    const int* __restrict__ eidx, const float* __restrict__ coords,
    const float* __restrict__ W1, const float* __restrict__ b1,
    const float* __restrict__ W2, const float* __restrict__ b2,
    const float* __restrict__ eng, const float* __restrict__ enb) {
    extern __shared__ __align__(16) float sm[];
    float* s_fe = sm;                       // region A: 128 x 76 (fe during prologue)
    float* s_H = sm;                        // region A reused: 128 x 68 (PQ / H in chunk loop)
    float* s_W1c = sm + 128 * 76;           // 72 x 72 fragment-major [k][g][t]
    float* s_W2c = s_W1c + 72 * 72;         // 64 x 40 fragment-major [j][g][t]
    float* s_b1 = s_W2c + 64 * 40;          // 648
    float* s_d2 = s_b1 + 648;               // 128
    int* s_src = (int*)(s_d2 + 128);        // 128
    int* s_dst = s_src + 128;               // 128

    int tid = threadIdx.x;
    int e0 = blockIdx.x << 7;

    if (tid < 128) {
        int e = e0 + tid;
        int s = eidx[e], d = eidx[NE + e];
        s_src[tid] = s; s_dst[tid] = d;
        float dx = coords[3 * s + 0] - coords[3 * d + 0];
        float dy = coords[3 * s + 1] - coords[3 * d + 1];
        float dz = coords[3 * s + 2] - coords[3 * d + 2];
        float d2 = dx * dx + dy * dy + dz * dz;
        s_d2[tid] = d2;
        s_fe[tid * 76 + 64] = to_tf32(d2);
#pragma unroll
        for (int j = 65; j < 72; j++) s_fe[tid * 76 + j] = 0.f;
    }
    for (int i = tid; i < 648; i += 256) s_b1[i] = (i < HID) ? b1[i] : 0.f;
    __syncthreads();
    for (int idx = tid; idx < 128 * 32; idx += 256) {
        int e = idx >> 5, i = idx & 31;
        float xs = s_d2[e] * __int_as_float((127 - i) << 23);
        float sv, cv;
        __sincosf(xs, &sv, &cv);
        s_fe[e * 76 + i] = to_tf32(sv);
        s_fe[e * 76 + 32 + i] = to_tf32(cv);
    }
    __syncthreads();  // fe complete

    int wid = tid >> 5, lane = tid & 31;
    int g = lane >> 2, tig = lane & 3;
    int r0 = wid << 4;
    int rlo = r0 + g, rhi = r0 + g + 8;

    // hoist fe A-fragments (chunk-invariant) into registers
    unsigned feA[9][4];
#pragma unroll
    for (int ks = 0; ks < 9; ks++) {
        int k0 = ks << 3;
        feA[ks][0] = __float_as_uint(s_fe[rlo * 76 + k0 + tig]);
        feA[ks][1] = __float_as_uint(s_fe[rhi * 76 + k0 + tig]);
        feA[ks][2] = __float_as_uint(s_fe[rlo * 76 + k0 + tig + 4]);
        feA[ks][3] = __float_as_uint(s_fe[rhi * 76 + k0 + tig + 4]);
    }
    // (s_fe region is now dead; the chunk loop's first __syncthreads orders
    //  the fragment reads above against the PQ staging writes into s_H below)

    float acc[4][4];
#pragma unroll
    for (int t = 0; t < 4; t++)
#pragma unroll
        for (int u = 0; u < 4; u++) acc[t][u] = 0.f;

    for (int c = 0; c < 11; c++) {
        int cb = c << 6;
        __syncthreads();  // A: prev GEMM2 done with smem; for c=0, fe fragment reads done
        for (int idx = tid; idx < 72 * 64; idx += 256) {
            int k = idx >> 6, n = idx & 63;
            int gj = cb + n;
            float v = (k < 65 && gj < HID) ? W1[(256 + k) * HID + gj] : 0.f;
            s_W1c[k * 72 + ((n & 7) << 3) + (n >> 3)] = to_tf32(v);
        }
        for (int idx = tid; idx < 64 * 32; idx += 256) {
            int j = idx >> 5, n = idx & 31;
            int gj = cb + j;
            float v = (gj < HID) ? W2[gj * MD + n] : 0.f;
            s_W2c[j * 40 + ((n & 7) << 2) + (n >> 3)] = to_tf32(v);
        }
        for (int it = tid; it < 128 * 16; it += 256) {
            int e = it >> 4, q = it & 15;
            int col = cb + (q << 2);
            float4 r = make_float4(0.f, 0.f, 0.f, 0.f);
            if (col < HID) {
                float4 pa = *(const float4*)&g_Pa[(size_t)s_dst[e] * PLD + col];
                float4 pb = *(const float4*)&g_Pb[(size_t)s_src[e] * PLD + col];
                r.x = pa.x + pb.x + s_b1[col];
                r.y = (col + 1 < HID) ? pa.y + pb.y + s_b1[col + 1] : 0.f;
                r.z = (col + 2 < HID) ? pa.z + pb.z + s_b1[col + 2] : 0.f;
                r.w = (col + 3 < HID) ? pa.w + pb.w + s_b1[col + 3] : 0.f;
            }
            *(float4*)&s_H[e * 68 + (q << 2)] = r;
        }
        __syncthreads();  // B: staging visible

        // GEMM1: c1 = FE @ W1c (A-fragments from registers)
        float c1[8][4];
#pragma unroll
        for (int t = 0; t < 8; t++)
#pragma unroll
            for (int u = 0; u < 4; u++) c1[t][u] = 0.f;
#pragma unroll
        for (int ks = 0; ks < 9; ks++) {
            int k0 = ks << 3;
            int bi0 = (k0 + tig) * 72 + (g << 3);
            int bi1 = (k0 + tig + 4) * 72 + (g << 3);
#pragma unroll
            for (int half = 0; half < 2; half++) {
                float w0[4], w1[4];
                *(float4*)w0 = *(const float4*)&s_W1c[bi0 + (half << 2)];
                *(float4*)w1 = *(const float4*)&s_W1c[bi1 + (half << 2)];
#pragma unroll
                for (int tt = 0; tt < 4; tt++) {
                    mma_tf32(c1[(half << 2) + tt], feA[ks][0], feA[ks][1], feA[ks][2], feA[ks][3],
                             __float_as_uint(w0[tt]), __float_as_uint(w1[tt]));
                }
            }
        }
#pragma unroll
        for (int t = 0; t < 8; t++) {
            int col = (t << 3) + (tig << 1);
            int i00 = rlo * 68 + col;
            int i10 = rhi * 68 + col;
            s_H[i00] = to_tf32(silu_f(c1[t][0] + s_H[i00]));
            s_H[i00 + 1] = to_tf32(silu_f(c1[t][1] + s_H[i00 + 1]));
            s_H[i10] = to_tf32(silu_f(c1[t][2] + s_H[i10]));
            s_H[i10 + 1] = to_tf32(silu_f(c1[t][3] + s_H[i10 + 1]));
        }
        __syncthreads();  // C: H visible

        // GEMM2: acc += H @ W2c
#pragma unroll
        for (int ks = 0; ks < 8; ks++) {
            int k0 = ks << 3;
            unsigned a0 = __float_as_uint(s_H[rlo * 68 + k0 + tig]);
            unsigned a1 = __float_as_uint(s_H[rhi * 68 + k0 + tig]);
            unsigned a2 = __float_as_uint(s_H[rlo * 68 + k0 + tig + 4]);
            unsigned a3 = __float_as_uint(s_H[rhi * 68 + k0 + tig + 4]);
            float w0[4], w1[4];
            *(float4*)w0 = *(const float4*)&s_W2c[(k0 + tig) * 40 + (g << 2)];
            *(float4*)w1 = *(const float4*)&s_W2c[(k0 + tig + 4) * 40 + (g << 2)];
#pragma unroll
            for (int t = 0; t < 4; t++) {
                mma_tf32(acc[t], a0, a1, a2, a3,
                         __float_as_uint(w0[t]), __float_as_uint(w1[t]));
            }
        }
    }

    int dlo = s_dst[rlo], dhi = s_dst[rhi];
    float vlo[8], vhi[8];
    float Slo = 0.f, Shi = 0.f;
#pragma unroll
    for (int t = 0; t < 4; t++) {
        int col = (t << 3) + (tig << 1);
        float v0 = silu_f(acc[t][0] + b2[col]);
        float v1 = silu_f(acc[t][1] + b2[col + 1]);
        float v2 = silu_f(acc[t][2] + b2[col]);
        float v3 = silu_f(acc[t][3] + b2[col + 1]);
        vlo[t * 2] = v0; vlo[t * 2 + 1] = v1;
        vhi[t * 2] = v2; vhi[t * 2 + 1] = v3;
        Slo += v0 + v1; Shi += v2 + v3;
    }
    Slo += __shfl_xor_sync(0xffffffffu, Slo, 1);
    Slo += __shfl_xor_sync(0xffffffffu, Slo, 2);
    Shi += __shfl_xor_sync(0xffffffffu, Shi, 1);
    Shi += __shfl_xor_sync(0xffffffffu, Shi, 2);
    float mlo = Slo * (1.f / 32.f), mhi = Shi * (1.f / 32.f);
    float Vlo = 0.f, Vhi = 0.f;
#pragma unroll
    for (int u = 0; u < 8; u++) {
        float d0 = vlo[u] - mlo; Vlo += d0 * d0;
        float d1 = vhi[u] - mhi; Vhi += d1 * d1;
    }
    Vlo += __shfl_xor_sync(0xffffffffu, Vlo, 1);
    Vlo += __shfl_xor_sync(0xffffffffu, Vlo, 2);
    Vhi += __shfl_xor_sync(0xffffffffu, Vhi, 1);
    Vhi += __shfl_xor_sync(0xffffffffu, Vhi, 2);
    float ilo = rsqrtf(Vlo * (1.f / 32.f) + EPSF);
    float ihi = rsqrtf(Vhi * (1.f / 32.f) + EPSF);
#pragma unroll
    for (int t = 0; t < 4; t++) {
#pragma unroll
        for (int d = 0; d < 2; d++) {
            int col = (t << 3) + (tig << 1) + d;
            atomicAdd(&g_seg[dlo * MD + col], (vlo[t * 2 + d] - mlo) * ilo * eng[col] + enb[col]);
            atomicAdd(&g_seg[dhi * MD + col], (vhi[t * 2 + d] - mhi) * ihi * eng[col] + enb[col]);
        }
    }
}

// ---------------- node pre ----------------
__global__ void k_node_pre(int off, const float* __restrict__ eng, const float* __restrict__ enb,
                           const float* __restrict__ n1g, const float* __restrict__ n1b) {
    int node = blockIdx.x * 8 + (threadIdx.x >> 5);
    int lane = threadIdx.x & 31;
    if (node >= NN) return;

    float x = g_seg[node * MD + lane] / fmaxf(g_cnt[node], 1.f);
    g_seg[node * MD + lane] = 0.f;
    float S = x;
#pragma unroll
    for (int o = 16; o; o >>= 1) S += __shfl_xor_sync(0xffffffffu, S, o);
    float mean = S * (1.f / 32.f);
    float d = x - mean;
    float V = d * d;
#pragma unroll
    for (int o = 16; o; o >>= 1) V += __shfl_xor_sync(0xffffffffu, V, o);
    V *= (1.f / 32.f);
    g_z[node * 160 + 128 + lane] = d * rsqrtf(V + EPSF) * eng[lane] + enb[lane];

    float4 v = *(const float4*)&g_cat[node * CAT + off + lane * 4];
    S = v.x + v.y + v.z + v.w;
#pragma unroll
    for (int o = 16; o; o >>= 1) S += __shfl_xor_sync(0xffffffffu, S, o);
    mean = S * (1.f / 128.f);
    float dx = v.x - mean, dy = v.y - mean, dz = v.z - mean, dw = v.w - mean;
    V = dx * dx + dy * dy + dz * dz + dw * dw;
#pragma unroll
    for (int o = 16; o; o >>= 1) V += __shfl_xor_sync(0xffffffffu, V, o);
    V *= (1.f / 128.f);
    float inv = rsqrtf(V + EPSF);
    float4 g4 = *(const float4*)&n1g[lane * 4];
    float4 b4 = *(const float4*)&n1b[lane * 4];
    float4 o4;
    o4.x = dx * inv * g4.x + b4.x;
    o4.y = dy * inv * g4.y + b4.y;
    o4.z = dz * inv * g4.z + b4.z;
    o4.w = dw * inv * g4.w + b4.w;
    *(float4*)&g_z[node * 160 + lane * 4] = o4;
}

// ---------------- node post ----------------
__global__ void k_node_post(int off, const float* __restrict__ n2g, const float* __restrict__ n2b) {
    int node = blockIdx.x * 8 + (threadIdx.x >> 5);
    int lane = threadIdx.x & 31;
    if (node >= NN) return;
    float4 v = *(const float4*)&g_h2[node * 128 + lane * 4];
    float S = v.x + v.y + v.z + v.w;
#pragma unroll
    for (int o = 16; o; o >>= 1) S += __shfl_xor_sync(0xffffffffu, S, o);
    float mean = S * (1.f / 128.f);
    float dx = v.x - mean, dy = v.y - mean, dz = v.z - mean, dw = v.w - mean;
    float V = dx * dx + dy * dy + dz * dz + dw * dw;
#pragma unroll
    for (int o = 16; o; o >>= 1) V += __shfl_xor_sync(0xffffffffu, V, o);
    V *= (1.f / 128.f);
    float inv = rsqrtf(V + EPSF);
    float4 g4 = *(const float4*)&n2g[lane * 4];
    float4 b4 = *(const float4*)&n2b[lane * 4];
    float4 old = *(const float4*)&g_cat[node * CAT + off + lane * 4];
    float4 o4;
    o4.x = old.x + dx * inv * g4.x + b4.x;
    o4.y = old.y + dy * inv * g4.y + b4.y;
    o4.z = old.z + dz * inv * g4.z + b4.z;
    o4.w = old.w + dw * inv * g4.w + b4.w;
    *(float4*)&g_cat[node * CAT + off + 128 + lane * 4] = o4;
    int base = node * EMB + lane * 4;
    float h;
    h = to_tf32(o4.x); g_Ah[base + 0] = h; g_Al[base + 0] = to_tf32(o4.x - h);
    h = to_tf32(o4.y); g_Ah[base + 1] = h; g_Al[base + 1] = to_tf32(o4.y - h);
    h = to_tf32(o4.z); g_Ah[base + 2] = h; g_Al[base + 2] = to_tf32(o4.z - h);
    h = to_tf32(o4.w); g_Ah[base + 3] = h; g_Al[base + 3] = to_tf32(o4.w - h);
}

// ---------------- graph head ----------------
__global__ void k_graph(const float* __restrict__ g1W, const float* __restrict__ g1b,
                        const float* __restrict__ g2W, const float* __restrict__ g2b,
                        const float* __restrict__ g3W, const float* __restrict__ g3b,
                        float* __restrict__ out) {
    __shared__ float h[256], t[256];
    int g = blockIdx.x, tid = threadIdx.x;
    float c = fmaxf(g_pcnt[g], 1.f);
    h[tid] = g_pool[g * 256 + tid] / c;
    __syncthreads();
    float a = g1b[tid];
    for (int k = 0; k < 256; k++) a += h[k] * g1W[k * 256 + tid];
    t[tid] = silu_f(a);
    __syncthreads();
    h[tid] = t[tid];
    __syncthreads();
    a = g2b[tid];
    for (int k = 0; k < 256; k++) a += h[k] * g2W[k * 256 + tid];
    t[tid] = silu_f(a);
    __syncthreads();
    h[tid] = t[tid];
    __syncthreads();
    t[tid] = h[tid] * g3W[tid];
    __syncthreads();
    for (int s = 128; s; s >>= 1) {
        if (tid < s) t[tid] += t[tid + s];
        __syncthreads();
    }
    if (tid == 0) out[g] = t[0] + g3b[0];
}

// ---------------- launch ----------------
extern "C" void kernel_launch(void* const* d_in, const int* in_sizes, int n_in,
                              void* d_out, int out_size) {
    const int* atomids = (const int*)d_in[0];
    const float* coords = (const float*)d_in[1];
    const int* eidx = (const int*)d_in[2];
    const int* batch = (const int*)d_in[3];
    const float* emb_w = (const float*)d_in[4];
    const float* eW1 = (const float*)d_in[5];
    const float* eb1 = (const float*)d_in[6];
    const float* eW2 = (const float*)d_in[7];
    const float* eb2 = (const float*)d_in[8];
    const float* en_g = (const float*)d_in[9];
    const float* en_b = (const float*)d_in[10];
    const float* nn1_g = (const float*)d_in[11];
    const float* nn1_b = (const float*)d_in[12];
    const float* nW1 = (const float*)d_in[13];
    const float* nb1 = (const float*)d_in[14];
    const float* nW2 = (const float*)d_in[15];
    const float* nb2 = (const float*)d_in[16];
    const float* nn2_g = (const float*)d_in[17];
    const float* nn2_b = (const float*)d_in[18];
    const float* f1W = (const float*)d_in[19];
    const float* f1b = (const float*)d_in[20];
    const float* f2W = (const float*)d_in[21];
    const float* f2b = (const float*)d_in[22];
    const float* f3W = (const float*)d_in[23];
    const float* f3b = (const float*)d_in[24];
    const float* g1W = (const float*)d_in[25];
    const float* g1b = (const float*)d_in[26];
    const float* g2W = (const float*)d_in[27];
    const float* g2b = (const float*)d_in[28];
    const float* g3W = (const float*)d_in[29];
    const float* g3b = (const float*)d_in[30];
    float* out = (float*)d_out;

    // edge smem: feH-region(128*76) + W1c(72*72) + W2c(64*40) + b1(648) + d2(128) + src/dst(256)
    const int smem_edge = (128 * 76 + 72 * 72 + 64 * 40 + 648 + 128 + 256) * 4;  // 74016 B
    cudaFuncSetAttribute(k_edge2, cudaFuncAttributeMaxDynamicSharedMemorySize, smem_edge);

    float *pcat, *pPa, *pPb, *pAh, *pAl, *pWh, *pWl, *pz, *ph1, *ph2, *pf1, *pf2, *pf3;
    cudaGetSymbolAddress((void**)&pcat, g_cat);
    cudaGetSymbolAddress((void**)&pPa, g_Pa);
    cudaGetSymbolAddress((void**)&pPb, g_Pb);
    cudaGetSymbolAddress((void**)&pAh, g_Ah);
    cudaGetSymbolAddress((void**)&pAl, g_Al);
    cudaGetSymbolAddress((void**)&pWh, g_Wh);
    cudaGetSymbolAddress((void**)&pWl, g_Wl);
    cudaGetSymbolAddress((void**)&pz, g_z);
    cudaGetSymbolAddress((void**)&ph1, g_h1);
    cudaGetSymbolAddress((void**)&ph2, g_h2);
    cudaGetSymbolAddress((void**)&pf1, g_f1);
    cudaGetSymbolAddress((void**)&pf2, g_f2);
    cudaGetSymbolAddress((void**)&pf3, g_f3);

    k_zero_start<<<(NN * MD + 255) / 256, 256>>>();
    k_deg<<<(NE + 255) / 256, 256>>>(eidx);
    k_embed<<<(NN * EMB + 255) / 256, 256>>>(atomids, emb_w);

    const int MB = (NN + 127) / 128;  // 79

    for (int k = 0; k < 5; k++) {
        int off = 128 * k;
        k_split_w<<<(256 * HID + 255) / 256, 256>>>(eW1 + (size_t)k * EIN * HID);
        k_gemm3p<<<dim3(22, MB), 256>>>(pAh, pAl, pWh, pWl, pPa, pPb);
        k_edge2<<<NE / 128, 256, smem_edge>>>(eidx, coords,
                                              eW1 + (size_t)k * EIN * HID, eb1 + k * HID,
                                              eW2 + (size_t)k * HID * MD, eb2 + k * MD,
                                              en_g + k * MD, en_b + k * MD);
        k_node_pre<<<NN / 8, 256>>>(off, en_g + k * MD, en_b + k * MD,
                                    nn1_g + k * EMB, nn1_b + k * EMB);
        k_gemm3t<<<dim3(4, MB), 256>>>(pz, nW1 + (size_t)k * 160 * 256, nb1 + k * 256, ph1,
                                       NN, 256, 160, 160, 256, 256, 1, 0);
        k_gemm3t<<<dim3(2, MB), 256>>>(ph1, nW2 + (size_t)k * 256 * 128, nb2 + k * 128, ph2,
                                       NN, 128, 256, 256, 128, 128, 0, 0);
        k_node_post<<<NN / 8, 256>>>(off, nn2_g + k * EMB, nn2_b + k * EMB);
    }

    k_gemm3t<<<dim3(4, MB), 256>>>(pcat, f1W, f1b, pf1, NN, 256, CAT, CAT, 256, 256, 1, 1);
    k_gemm3t<<<dim3(4, MB), 256>>>(pf1, f2W, f2b, pf2, NN, 256, 256, 256, 256, 256, 1, 0);
    k_gemm3t<<<dim3(4, MB), 256>>>(pf2, f3W, f3b, pf3, NN, 256, 256, 256, 256, 256, 1, 0);
    k_pool<<<(NN * 256 + 255) / 256, 256>>>(batch);
    k_graph<<<NG, 256>>>(g1W, g1b, g2W, g2b, g3W, g3b, out);
}